// round 3
// baseline (speedup 1.0000x reference)
#include <cuda_runtime.h>

// Problem constants (fixed shapes from reference)
#define BB   2
#define SS   2048
#define HIDD 2048
#define NH   16
#define NKV  4
#define HD   128
#define KVD  (NKV * HD)   // 512

// Scratch (allocation-free rule: __device__ globals)
__device__ float g_q[BB * SS * HIDD];   // [B,S,H,HD]
__device__ float g_k[BB * SS * KVD];    // [B,S,KVH,HD]
__device__ float g_v[BB * SS * KVD];    // [B,S,KVH,HD]
__device__ float g_y[BB * SS * HIDD];   // [B,S,HID]

typedef unsigned long long u64;

// ---- packed f32x2 helpers (Blackwell FFMA2: 2 FMAs per issue slot) ----
__device__ __forceinline__ void fma2(u64 &d, u64 a, u64 b) {
    asm("fma.rn.f32x2 %0, %1, %2, %0;" : "+l"(d) : "l"(a), "l"(b));
}
__device__ __forceinline__ u64 mul2(u64 a, u64 b) {
    u64 r; asm("mul.rn.f32x2 %0, %1, %2;" : "=l"(r) : "l"(a), "l"(b)); return r;
}
__device__ __forceinline__ u64 dup2(float a) {
    u64 r; asm("mov.b64 %0, {%1, %1};" : "=l"(r) : "f"(a)); return r;
}
__device__ __forceinline__ float hadd2(u64 v) {
    float lo, hi; asm("mov.b64 {%0, %1}, %2;" : "=f"(lo), "=f"(hi) : "l"(v));
    return lo + hi;
}
__device__ __forceinline__ void unpack2(u64 v, float &lo, float &hi) {
    asm("mov.b64 {%0, %1}, %2;" : "=f"(lo), "=f"(hi) : "l"(v));
}

// ============================================================================
// SGEMM: C[M,N] = A[M,K] @ B[N,K]^T  (all row-major; M,N % 128 == 0, K % 8 == 0)
// 128x128 block tile, BK=8, 8x8 thread tile, f32x2 over adjacent N columns.
// ============================================================================
__global__ __launch_bounds__(256) void sgemm_nt(
    const float* __restrict__ A, const float* __restrict__ B,
    float* __restrict__ C, int M, int N, int K)
{
    __shared__ __align__(16) float As[8][132];
    __shared__ __align__(16) float Bs[8][132];

    int tid = threadIdx.x;
    int tx = tid & 15, ty = tid >> 4;
    int m0 = blockIdx.y * 128, n0 = blockIdx.x * 128;

    int lrow = tid >> 1;           // 0..127
    int lcol = (tid & 1) * 4;      // 0 or 4
    const float* Ag = A + (m0 + lrow) * K + lcol;
    const float* Bg = B + (n0 + lrow) * K + lcol;

    u64 acc[8][4];
    #pragma unroll
    for (int i = 0; i < 8; i++)
        #pragma unroll
        for (int j = 0; j < 4; j++) acc[i][j] = 0ull;

    for (int kt = 0; kt < K; kt += 8) {
        float4 av = *(const float4*)(Ag + kt);
        float4 bv = *(const float4*)(Bg + kt);
        As[lcol + 0][lrow] = av.x; As[lcol + 1][lrow] = av.y;
        As[lcol + 2][lrow] = av.z; As[lcol + 3][lrow] = av.w;
        Bs[lcol + 0][lrow] = bv.x; Bs[lcol + 1][lrow] = bv.y;
        Bs[lcol + 2][lrow] = bv.z; Bs[lcol + 3][lrow] = bv.w;
        __syncthreads();

        #pragma unroll
        for (int k = 0; k < 8; k++) {
            u64 b2[4];
            ulonglong2 t0 = *(const ulonglong2*)&Bs[k][tx * 8];
            ulonglong2 t1 = *(const ulonglong2*)&Bs[k][tx * 8 + 4];
            b2[0] = t0.x; b2[1] = t0.y; b2[2] = t1.x; b2[3] = t1.y;
            #pragma unroll
            for (int i = 0; i < 8; i++) {
                u64 a2 = dup2(As[k][ty * 8 + i]);
                fma2(acc[i][0], a2, b2[0]);
                fma2(acc[i][1], a2, b2[1]);
                fma2(acc[i][2], a2, b2[2]);
                fma2(acc[i][3], a2, b2[3]);
            }
        }
        __syncthreads();
    }

    #pragma unroll
    for (int i = 0; i < 8; i++) {
        float r[8];
        #pragma unroll
        for (int j = 0; j < 4; j++) unpack2(acc[i][j], r[2 * j], r[2 * j + 1]);
        float* dst = C + (m0 + ty * 8 + i) * N + n0 + tx * 8;
        *(float4*)(dst)     = make_float4(r[0], r[1], r[2], r[3]);
        *(float4*)(dst + 4) = make_float4(r[4], r[5], r[6], r[7]);
    }
}

// ============================================================================
// RoPE applied in-place to Q [B,S,H,HD] and K [B,S,KVH,HD]
// pair i: (x[2i], x[2i+1]) rotated by (cos[s,i], sin[s,i])
// ============================================================================
__global__ void rope_kernel(float* __restrict__ q, float* __restrict__ k,
                            const float* __restrict__ cs, const float* __restrict__ sn)
{
    int idx = blockIdx.x * blockDim.x + threadIdx.x;
    int i = idx & 63;
    int rest = idx >> 6;
    int hh = rest % (NH + NKV);
    rest /= (NH + NKV);
    int s = rest % SS;
    int b = rest / SS;

    float c = cs[s * 64 + i];
    float sv = sn[s * 64 + i];
    float* p;
    if (hh < NH) p = q + ((b * SS + s) * NH + hh) * HD + 2 * i;
    else         p = k + ((b * SS + s) * NKV + (hh - NH)) * HD + 2 * i;
    float e = p[0], o = p[1];
    p[0] = e * c - o * sv;
    p[1] = e * sv + o * c;
}

// ============================================================================
// Causal flash attention, fp32 online softmax, f32x2 packed math.
// Bq = Bk = 64, HD = 128, 256 threads (16x16), GQA: kvh = h/4.
// Thread (ty,tx): S rows r = ty*4+i, S cols c = tx+16*j (j<4),
//                 O rows r, O cols col = tx+16*j (j<8).
// ============================================================================
#define FLASH_SMEM_FLOATS (2 * 64 * 132 + 128 * 66 + 64 * 66)
#define FLASH_SMEM_BYTES  (FLASH_SMEM_FLOATS * 4)

__global__ __launch_bounds__(256, 1) void flash_fwd(
    const float* __restrict__ Q, const float* __restrict__ K,
    const float* __restrict__ V, float* __restrict__ Y)
{
    extern __shared__ __align__(16) float sm[];
    float* Qs = sm;                      // [64][132]
    float* Ks = sm + 64 * 132;           // [64][132]
    float* Vt = sm + 2 * 64 * 132;       // [128][66] transposed (dim-major)
    float* Ps = sm + 2 * 64 * 132 + 128 * 66;  // [64][66]

    int tid = threadIdx.x;
    int tx = tid & 15, ty = tid >> 4;
    int qb = blockIdx.x, h = blockIdx.y, b = blockIdx.z;
    int kvh = h >> 2;                   // NH/NKV = 4
    int q0 = qb * 64;

    // Load Q tile (64 x 128), coalesced float4
    const float* Qg = Q + ((b * SS + q0) * NH + h) * HD;
    #pragma unroll
    for (int it = 0; it < 8; it++) {
        int idx = tid + it * 256;
        int r = idx >> 5, c4 = (idx & 31) * 4;
        *(float4*)&Qs[r * 132 + c4] = *(const float4*)(Qg + r * (NH * HD) + c4);
    }

    float m_i[4], l_i[4];
    u64 o2[4][8];
    #pragma unroll
    for (int i = 0; i < 4; i++) {
        m_i[i] = -1e30f; l_i[i] = 0.f;
        #pragma unroll
        for (int j = 0; j < 8; j++) o2[i][j] = 0ull;
    }
    const float scale = 0.088388347648318447f;   // 1/sqrt(128)

    for (int kt = 0; kt <= qb; kt++) {
        int k0 = kt * 64;
        const float* Kg = K + ((b * SS + k0) * NKV + kvh) * HD;
        const float* Vg = V + ((b * SS + k0) * NKV + kvh) * HD;

        __syncthreads();   // Q ready (first iter) / prev-iter PV finished
        #pragma unroll
        for (int it = 0; it < 8; it++) {
            int idx = tid + it * 256;
            int r = idx >> 5, c4 = (idx & 31) * 4;
            *(float4*)&Ks[r * 132 + c4] = *(const float4*)(Kg + r * (NKV * HD) + c4);
            float4 vv = *(const float4*)(Vg + r * (NKV * HD) + c4);
            Vt[(c4 + 0) * 66 + r] = vv.x;
            Vt[(c4 + 1) * 66 + r] = vv.y;
            Vt[(c4 + 2) * 66 + r] = vv.z;
            Vt[(c4 + 3) * 66 + r] = vv.w;
        }
        __syncthreads();

        // ---- S = Q K^T (f32x2 over d-pairs, horizontal add at end) ----
        u64 s2[4][4];
        #pragma unroll
        for (int i = 0; i < 4; i++)
            #pragma unroll
            for (int j = 0; j < 4; j++) s2[i][j] = 0ull;

        #pragma unroll 4
        for (int d4 = 0; d4 < 32; d4++) {
            ulonglong2 qv[4], kv[4];
            #pragma unroll
            for (int i = 0; i < 4; i++)
                qv[i] = *(const ulonglong2*)&Qs[(ty * 4 + i) * 132 + d4 * 4];
            #pragma unroll
            for (int j = 0; j < 4; j++)
                kv[j] = *(const ulonglong2*)&Ks[(tx + 16 * j) * 132 + d4 * 4];
            #pragma unroll
            for (int i = 0; i < 4; i++)
                #pragma unroll
                for (int j = 0; j < 4; j++) {
                    fma2(s2[i][j], qv[i].x, kv[j].x);
                    fma2(s2[i][j], qv[i].y, kv[j].y);
                }
        }

        // ---- online softmax update ----
        float p[4][4];
        bool diag = (kt == qb);
        #pragma unroll
        for (int i = 0; i < 4; i++)
            #pragma unroll
            for (int j = 0; j < 4; j++) {
                float sv = hadd2(s2[i][j]) * scale;
                if (diag && (tx + 16 * j) > (ty * 4 + i)) sv = -1e30f;
                p[i][j] = sv;
            }

        #pragma unroll
        for (int i = 0; i < 4; i++) {
            float mx = fmaxf(fmaxf(p[i][0], p[i][1]), fmaxf(p[i][2], p[i][3]));
            #pragma unroll
            for (int off = 8; off; off >>= 1)
                mx = fmaxf(mx, __shfl_xor_sync(0xffffffffu, mx, off));
            float mn = fmaxf(m_i[i], mx);
            float al = __expf(m_i[i] - mn);
            m_i[i] = mn;
            float rs = 0.f;
            #pragma unroll
            for (int j = 0; j < 4; j++) {
                float e = __expf(p[i][j] - mn);
                p[i][j] = e; rs += e;
            }
            #pragma unroll
            for (int off = 8; off; off >>= 1)
                rs += __shfl_xor_sync(0xffffffffu, rs, off);
            l_i[i] = l_i[i] * al + rs;
            u64 al2 = dup2(al);
            #pragma unroll
            for (int j = 0; j < 8; j++) o2[i][j] = mul2(o2[i][j], al2);
            #pragma unroll
            for (int j = 0; j < 4; j++)
                Ps[(ty * 4 + i) * 66 + tx + 16 * j] = p[i][j];
        }
        __syncthreads();

        // ---- O += P @ V (f32x2 over c-pairs via transposed V tile) ----
        #pragma unroll 4
        for (int cp = 0; cp < 32; cp++) {
            u64 p2[4], v2[8];
            #pragma unroll
            for (int i = 0; i < 4; i++)
                p2[i] = *(const u64*)&Ps[(ty * 4 + i) * 66 + cp * 2];
            #pragma unroll
            for (int j = 0; j < 8; j++)
                v2[j] = *(const u64*)&Vt[(tx + 16 * j) * 66 + cp * 2];
            #pragma unroll
            for (int i = 0; i < 4; i++)
                #pragma unroll
                for (int j = 0; j < 8; j++)
                    fma2(o2[i][j], p2[i], v2[j]);
        }
    }

    // ---- epilogue: Y[b, q0+r, h*HD + col] = O / l ----
    float* Yg = Y + (b * SS + q0) * HIDD + h * HD;
    #pragma unroll
    for (int i = 0; i < 4; i++) {
        float inv = 1.0f / l_i[i];
        int r = ty * 4 + i;
        #pragma unroll
        for (int j = 0; j < 8; j++)
            Yg[r * HIDD + tx + 16 * j] = hadd2(o2[i][j]) * inv;
    }
}

// ============================================================================
// Launch
// ============================================================================
extern "C" void kernel_launch(void* const* d_in, const int* in_sizes, int n_in,
                              void* d_out, int out_size)
{
    const float* x  = (const float*)d_in[0];
    const float* cs = (const float*)d_in[1];
    const float* sn = (const float*)d_in[2];
    const float* Wq = (const float*)d_in[3];
    const float* Wk = (const float*)d_in[4];
    const float* Wv = (const float*)d_in[5];
    const float* Wo = (const float*)d_in[6];
    float* out = (float*)d_out;

    float *qp, *kp, *vp, *yp;
    cudaGetSymbolAddress((void**)&qp, g_q);
    cudaGetSymbolAddress((void**)&kp, g_k);
    cudaGetSymbolAddress((void**)&vp, g_v);
    cudaGetSymbolAddress((void**)&yp, g_y);

    const int M = BB * SS;   // 4096

    sgemm_nt<<<dim3(HIDD / 128, M / 128), 256>>>(x, Wq, qp, M, HIDD, HIDD);
    sgemm_nt<<<dim3(KVD  / 128, M / 128), 256>>>(x, Wk, kp, M, KVD,  HIDD);
    sgemm_nt<<<dim3(KVD  / 128, M / 128), 256>>>(x, Wv, vp, M, KVD,  HIDD);

    rope_kernel<<<(BB * SS * (NH + NKV) * (HD / 2)) / 256, 256>>>(qp, kp, cs, sn);

    cudaFuncSetAttribute(flash_fwd, cudaFuncAttributeMaxDynamicSharedMemorySize,
                         FLASH_SMEM_BYTES);
    flash_fwd<<<dim3(SS / 64, NH, BB), 256, FLASH_SMEM_BYTES>>>(qp, kp, vp, yp);

    sgemm_nt<<<dim3(HIDD / 128, M / 128), 256>>>(yp, Wo, out, M, HIDD, HIDD);
}

// round 6
// speedup vs baseline: 1.7848x; 1.7848x over previous
#include <cuda_runtime.h>
#include <cstdint>

// Problem constants (fixed shapes from reference)
#define BB   2
#define SS   2048
#define HIDD 2048
#define NH   16
#define NKV  4
#define HD   128
#define KVD  (NKV * HD)   // 512

// Scratch (allocation-free rule: __device__ globals)
__device__ float g_q[BB * SS * HIDD];    // [B,S,H,HD]
__device__ float g_k[BB * SS * KVD];     // [B,S,KVH,HD]
__device__ float g_v[BB * SS * KVD];     // [B,S,KVH,HD]
__device__ float g_y[BB * SS * HIDD];    // [B,S,HID] (tf32-rounded by flash)
__device__ float g_xc[BB * SS * HIDD];   // tf32-rounded x
__device__ float g_wq[HIDD * HIDD];      // tf32-rounded weights
__device__ float g_wk[KVD * HIDD];
__device__ float g_wv[KVD * HIDD];
__device__ float g_wo[HIDD * HIDD];

typedef unsigned long long u64;

// ---- packed f32x2 helpers (flash kernel) ----
__device__ __forceinline__ void fma2(u64 &d, u64 a, u64 b) {
    asm("fma.rn.f32x2 %0, %1, %2, %0;" : "+l"(d) : "l"(a), "l"(b));
}
__device__ __forceinline__ u64 mul2(u64 a, u64 b) {
    u64 r; asm("mul.rn.f32x2 %0, %1, %2;" : "=l"(r) : "l"(a), "l"(b)); return r;
}
__device__ __forceinline__ u64 dup2(float a) {
    u64 r; asm("mov.b64 %0, {%1, %1};" : "=l"(r) : "f"(a)); return r;
}
__device__ __forceinline__ float hadd2(u64 v) {
    float lo, hi; asm("mov.b64 {%0, %1}, %2;" : "=f"(lo), "=f"(hi) : "l"(v));
    return lo + hi;
}

// ---- misc helpers ----
__device__ __forceinline__ uint32_t smem_u32(const void* p) {
    uint32_t a;
    asm("{ .reg .u64 t; cvta.to.shared.u64 t, %1; cvt.u32.u64 %0, t; }"
        : "=r"(a) : "l"(p));
    return a;
}
__device__ __forceinline__ uint32_t f2tf32(float f) {
    uint32_t t; asm("cvt.rna.tf32.f32 %0, %1;" : "=r"(t) : "f"(f)); return t;
}
__device__ __forceinline__ void cp_async16(uint32_t dst, const void* src) {
    asm volatile("cp.async.cg.shared.global [%0], [%1], 16;" :: "r"(dst), "l"(src));
}
#define CP_COMMIT() asm volatile("cp.async.commit_group;" ::: "memory")
#define CP_WAIT2()  asm volatile("cp.async.wait_group 2;" ::: "memory")

// mma.sync tf32 m16n8k8 (base sm_80+ PTX -> legacy HMMA on sm_103; no 'a' needed)
__device__ __forceinline__ void mma_tf32(float* c, const uint32_t* a, const uint32_t* b) {
    asm volatile(
        "mma.sync.aligned.m16n8k8.row.col.f32.tf32.tf32.f32 "
        "{%0,%1,%2,%3}, {%4,%5,%6,%7}, {%8,%9}, {%0,%1,%2,%3};"
        : "+f"(c[0]), "+f"(c[1]), "+f"(c[2]), "+f"(c[3])
        : "r"(a[0]), "r"(a[1]), "r"(a[2]), "r"(a[3]), "r"(b[0]), "r"(b[1]));
}

// ============================================================================
// Elementwise tf32 rounding (RN): out[i] = tf32(in[i]); n % 4 == 0
// ============================================================================
__global__ void tf32_cvt(const float* __restrict__ in, float* __restrict__ out, int n)
{
    int i = (blockIdx.x * blockDim.x + threadIdx.x) * 4;
    if (i >= n) return;
    float4 v = *(const float4*)(in + i);
    uint4 o;
    o.x = f2tf32(v.x); o.y = f2tf32(v.y); o.z = f2tf32(v.z); o.w = f2tf32(v.w);
    *(uint4*)(out + i) = o;
}

// ============================================================================
// TF32 mma.sync GEMM:  C[M,N] = A[M,K] @ B[N,K]^T  (row-major; M,N%128, K%16)
// A, B must be pre-rounded to tf32 bit patterns.
// 128x128 CTA tile, 8 warps of 32x64, K-chunk 16, 4-stage cp.async ring.
// Smem rows padded to stride 20 floats -> conflict-free fragment LDS.
// ============================================================================
#define GSTAGE_FLOATS 5120              // A 128*20 + B 128*20
#define GSMEM_BYTES  (4 * GSTAGE_FLOATS * 4)   // 81920

__device__ __forceinline__ void gemm_load_stage(
    uint32_t sbase, const float* __restrict__ Ag, const float* __restrict__ Bg,
    int K, int kt, int tid)
{
    int row = tid >> 1;
    int half = (tid & 1) * 8;           // 8-float half of the 16-float chunk
    const float* sa = Ag + (size_t)row * K + kt * 16 + half;
    const float* sb = Bg + (size_t)row * K + kt * 16 + half;
    uint32_t da = sbase + (row * 20 + half) * 4;
    uint32_t db = sbase + (2560 + row * 20 + half) * 4;
    cp_async16(da, sa);       cp_async16(da + 16, sa + 4);
    cp_async16(db, sb);       cp_async16(db + 16, sb + 4);
}

__global__ __launch_bounds__(256) void gemm_mma(
    const float* __restrict__ A, const float* __restrict__ B,
    float* __restrict__ C, int M, int N, int K)
{
    extern __shared__ __align__(16) float sm[];
    int tid = threadIdx.x;
    int lane = tid & 31, wid = tid >> 5;
    int gid = lane >> 2, tig = lane & 3;
    int wm = wid & 3, wn = wid >> 2;                 // warp tile: rows wm*32, cols wn*64
    int m0 = blockIdx.y * 128, n0 = blockIdx.x * 128;

    const float* Ag = A + (size_t)m0 * K;
    const float* Bg = B + (size_t)n0 * K;
    uint32_t sb0 = smem_u32(sm);
    int nk = K / 16;

    float acc[2][8][4];
    #pragma unroll
    for (int i = 0; i < 2; i++)
        #pragma unroll
        for (int j = 0; j < 8; j++)
            #pragma unroll
            for (int r = 0; r < 4; r++) acc[i][j][r] = 0.f;

    // prologue: stages 0..2
    #pragma unroll
    for (int s = 0; s < 3; s++) {
        gemm_load_stage(sb0 + s * GSTAGE_FLOATS * 4, Ag, Bg, K, s, tid);
        CP_COMMIT();
    }

    for (int s = 0; s < nk; s++) {
        CP_WAIT2();
        __syncthreads();
        if (s + 3 < nk)
            gemm_load_stage(sb0 + ((s + 3) & 3) * GSTAGE_FLOATS * 4, Ag, Bg, K, s + 3, tid);
        CP_COMMIT();

        const float* Asf = sm + (s & 3) * GSTAGE_FLOATS;
        const float* Bsf = Asf + 2560;

        #pragma unroll
        for (int ks = 0; ks < 2; ks++) {
            int kb = ks * 8;
            uint32_t af[2][4], bf[8][2];
            #pragma unroll
            for (int mt = 0; mt < 2; mt++) {
                int r = wm * 32 + mt * 16 + gid;
                af[mt][0] = __float_as_uint(Asf[r * 20 + kb + tig]);
                af[mt][1] = __float_as_uint(Asf[(r + 8) * 20 + kb + tig]);
                af[mt][2] = __float_as_uint(Asf[r * 20 + kb + tig + 4]);
                af[mt][3] = __float_as_uint(Asf[(r + 8) * 20 + kb + tig + 4]);
            }
            #pragma unroll
            for (int nt = 0; nt < 8; nt++) {
                int nn = wn * 64 + nt * 8 + gid;
                bf[nt][0] = __float_as_uint(Bsf[nn * 20 + kb + tig]);
                bf[nt][1] = __float_as_uint(Bsf[nn * 20 + kb + tig + 4]);
            }
            #pragma unroll
            for (int mt = 0; mt < 2; mt++)
                #pragma unroll
                for (int nt = 0; nt < 8; nt++)
                    mma_tf32(acc[mt][nt], af[mt], bf[nt]);
        }
        __syncthreads();
    }

    // epilogue: direct STG.64 (4 lanes x 8B = full 32B sectors per row)
    #pragma unroll
    for (int mt = 0; mt < 2; mt++) {
        int r = m0 + wm * 32 + mt * 16 + gid;
        #pragma unroll
        for (int nt = 0; nt < 8; nt++) {
            int cc = n0 + wn * 64 + nt * 8 + 2 * tig;
            *(float2*)&C[(size_t)r * N + cc]       = make_float2(acc[mt][nt][0], acc[mt][nt][1]);
            *(float2*)&C[(size_t)(r + 8) * N + cc] = make_float2(acc[mt][nt][2], acc[mt][nt][3]);
        }
    }
}

// ============================================================================
// RoPE applied in-place to Q [B,S,H,HD] and K [B,S,KVH,HD]
// ============================================================================
__global__ void rope_kernel(float* __restrict__ q, float* __restrict__ k,
                            const float* __restrict__ cs, const float* __restrict__ sn)
{
    int idx = blockIdx.x * blockDim.x + threadIdx.x;
    int i = idx & 63;
    int rest = idx >> 6;
    int hh = rest % (NH + NKV);
    rest /= (NH + NKV);
    int s = rest % SS;
    int b = rest / SS;

    float c = cs[s * 64 + i];
    float sv = sn[s * 64 + i];
    float* p;
    if (hh < NH) p = q + ((b * SS + s) * NH + hh) * HD + 2 * i;
    else         p = k + ((b * SS + s) * NKV + (hh - NH)) * HD + 2 * i;
    float e = p[0], o = p[1];
    p[0] = e * c - o * sv;
    p[1] = e * sv + o * c;
}

// ============================================================================
// Causal flash attention, fp32 online softmax, f32x2 packed math.
// Output written tf32-rounded (feeds the mma output projection).
// ============================================================================
#define FLASH_SMEM_FLOATS (2 * 64 * 132 + 128 * 66 + 64 * 66)
#define FLASH_SMEM_BYTES  (FLASH_SMEM_FLOATS * 4)

__global__ __launch_bounds__(256, 1) void flash_fwd(
    const float* __restrict__ Q, const float* __restrict__ K,
    const float* __restrict__ V, float* __restrict__ Y)
{
    extern __shared__ __align__(16) float sm[];
    float* Qs = sm;                      // [64][132]
    float* Ks = sm + 64 * 132;           // [64][132]
    float* Vt = sm + 2 * 64 * 132;       // [128][66] transposed
    float* Ps = sm + 2 * 64 * 132 + 128 * 66;  // [64][66]

    int tid = threadIdx.x;
    int tx = tid & 15, ty = tid >> 4;
    int qb = blockIdx.x, h = blockIdx.y, b = blockIdx.z;
    int kvh = h >> 2;
    int q0 = qb * 64;

    const float* Qg = Q + ((b * SS + q0) * NH + h) * HD;
    #pragma unroll
    for (int it = 0; it < 8; it++) {
        int idx = tid + it * 256;
        int r = idx >> 5, c4 = (idx & 31) * 4;
        *(float4*)&Qs[r * 132 + c4] = *(const float4*)(Qg + r * (NH * HD) + c4);
    }

    float m_i[4], l_i[4];
    u64 o2[4][8];
    #pragma unroll
    for (int i = 0; i < 4; i++) {
        m_i[i] = -1e30f; l_i[i] = 0.f;
        #pragma unroll
        for (int j = 0; j < 8; j++) o2[i][j] = 0ull;
    }
    const float scale = 0.088388347648318447f;

    for (int kt = 0; kt <= qb; kt++) {
        int k0 = kt * 64;
        const float* Kg = K + ((b * SS + k0) * NKV + kvh) * HD;
        const float* Vg = V + ((b * SS + k0) * NKV + kvh) * HD;

        __syncthreads();
        #pragma unroll
        for (int it = 0; it < 8; it++) {
            int idx = tid + it * 256;
            int r = idx >> 5, c4 = (idx & 31) * 4;
            *(float4*)&Ks[r * 132 + c4] = *(const float4*)(Kg + r * (NKV * HD) + c4);
            float4 vv = *(const float4*)(Vg + r * (NKV * HD) + c4);
            Vt[(c4 + 0) * 66 + r] = vv.x;
            Vt[(c4 + 1) * 66 + r] = vv.y;
            Vt[(c4 + 2) * 66 + r] = vv.z;
            Vt[(c4 + 3) * 66 + r] = vv.w;
        }
        __syncthreads();

        u64 s2[4][4];
        #pragma unroll
        for (int i = 0; i < 4; i++)
            #pragma unroll
            for (int j = 0; j < 4; j++) s2[i][j] = 0ull;

        #pragma unroll 4
        for (int d4 = 0; d4 < 32; d4++) {
            ulonglong2 qv[4], kv[4];
            #pragma unroll
            for (int i = 0; i < 4; i++)
                qv[i] = *(const ulonglong2*)&Qs[(ty * 4 + i) * 132 + d4 * 4];
            #pragma unroll
            for (int j = 0; j < 4; j++)
                kv[j] = *(const ulonglong2*)&Ks[(tx + 16 * j) * 132 + d4 * 4];
            #pragma unroll
            for (int i = 0; i < 4; i++)
                #pragma unroll
                for (int j = 0; j < 4; j++) {
                    fma2(s2[i][j], qv[i].x, kv[j].x);
                    fma2(s2[i][j], qv[i].y, kv[j].y);
                }
        }

        float p[4][4];
        bool diag = (kt == qb);
        #pragma unroll
        for (int i = 0; i < 4; i++)
            #pragma unroll
            for (int j = 0; j < 4; j++) {
                float sv = hadd2(s2[i][j]) * scale;
                if (diag && (tx + 16 * j) > (ty * 4 + i)) sv = -1e30f;
                p[i][j] = sv;
            }

        #pragma unroll
        for (int i = 0; i < 4; i++) {
            float mx = fmaxf(fmaxf(p[i][0], p[i][1]), fmaxf(p[i][2], p[i][3]));
            #pragma unroll
            for (int off = 8; off; off >>= 1)
                mx = fmaxf(mx, __shfl_xor_sync(0xffffffffu, mx, off));
            float mn = fmaxf(m_i[i], mx);
            float al = __expf(m_i[i] - mn);
            m_i[i] = mn;
            float rs = 0.f;
            #pragma unroll
            for (int j = 0; j < 4; j++) {
                float e = __expf(p[i][j] - mn);
                p[i][j] = e; rs += e;
            }
            #pragma unroll
            for (int off = 8; off; off >>= 1)
                rs += __shfl_xor_sync(0xffffffffu, rs, off);
            l_i[i] = l_i[i] * al + rs;
            u64 al2 = dup2(al);
            #pragma unroll
            for (int j = 0; j < 8; j++) o2[i][j] = mul2(o2[i][j], al2);
            #pragma unroll
            for (int j = 0; j < 4; j++)
                Ps[(ty * 4 + i) * 66 + tx + 16 * j] = p[i][j];
        }
        __syncthreads();

        #pragma unroll 4
        for (int cp = 0; cp < 32; cp++) {
            u64 p2[4], v2[8];
            #pragma unroll
            for (int i = 0; i < 4; i++)
                p2[i] = *(const u64*)&Ps[(ty * 4 + i) * 66 + cp * 2];
            #pragma unroll
            for (int j = 0; j < 8; j++)
                v2[j] = *(const u64*)&Vt[(tx + 16 * j) * 66 + cp * 2];
            #pragma unroll
            for (int i = 0; i < 4; i++)
                #pragma unroll
                for (int j = 0; j < 8; j++)
                    fma2(o2[i][j], p2[i], v2[j]);
        }
    }

    // epilogue: emit tf32-rounded output (next gemm's A operand)
    float* Yg = Y + (b * SS + q0) * HIDD + h * HD;
    #pragma unroll
    for (int i = 0; i < 4; i++) {
        float inv = 1.0f / l_i[i];
        int r = ty * 4 + i;
        #pragma unroll
        for (int j = 0; j < 8; j++) {
            uint32_t t = f2tf32(hadd2(o2[i][j]) * inv);
            Yg[r * HIDD + tx + 16 * j] = __uint_as_float(t);
        }
    }
}

// ============================================================================
// Launch
// ============================================================================
extern "C" void kernel_launch(void* const* d_in, const int* in_sizes, int n_in,
                              void* d_out, int out_size)
{
    const float* x  = (const float*)d_in[0];
    const float* cs = (const float*)d_in[1];
    const float* sn = (const float*)d_in[2];
    const float* Wq = (const float*)d_in[3];
    const float* Wk = (const float*)d_in[4];
    const float* Wv = (const float*)d_in[5];
    const float* Wo = (const float*)d_in[6];
    float* out = (float*)d_out;

    float *qp, *kp, *vp, *yp, *xc, *wq, *wk, *wv, *wo;
    cudaGetSymbolAddress((void**)&qp, g_q);
    cudaGetSymbolAddress((void**)&kp, g_k);
    cudaGetSymbolAddress((void**)&vp, g_v);
    cudaGetSymbolAddress((void**)&yp, g_y);
    cudaGetSymbolAddress((void**)&xc, g_xc);
    cudaGetSymbolAddress((void**)&wq, g_wq);
    cudaGetSymbolAddress((void**)&wk, g_wk);
    cudaGetSymbolAddress((void**)&wv, g_wv);
    cudaGetSymbolAddress((void**)&wo, g_wo);

    const int M = BB * SS;   // 4096

    cudaFuncSetAttribute(gemm_mma, cudaFuncAttributeMaxDynamicSharedMemorySize, GSMEM_BYTES);
    cudaFuncSetAttribute(flash_fwd, cudaFuncAttributeMaxDynamicSharedMemorySize, FLASH_SMEM_BYTES);

    // one-shot tf32 rounding of GEMM operands
    tf32_cvt<<<(M * HIDD / 4 + 255) / 256, 256>>>(x, xc, M * HIDD);
    tf32_cvt<<<(HIDD * HIDD / 4 + 255) / 256, 256>>>(Wq, wq, HIDD * HIDD);
    tf32_cvt<<<(KVD * HIDD / 4 + 255) / 256, 256>>>(Wk, wk, KVD * HIDD);
    tf32_cvt<<<(KVD * HIDD / 4 + 255) / 256, 256>>>(Wv, wv, KVD * HIDD);
    tf32_cvt<<<(HIDD * HIDD / 4 + 255) / 256, 256>>>(Wo, wo, HIDD * HIDD);

    gemm_mma<<<dim3(HIDD / 128, M / 128), 256, GSMEM_BYTES>>>(xc, wq, qp, M, HIDD, HIDD);
    gemm_mma<<<dim3(KVD  / 128, M / 128), 256, GSMEM_BYTES>>>(xc, wk, kp, M, KVD,  HIDD);
    gemm_mma<<<dim3(KVD  / 128, M / 128), 256, GSMEM_BYTES>>>(xc, wv, vp, M, KVD,  HIDD);

    rope_kernel<<<(BB * SS * (NH + NKV) * (HD / 2)) / 256, 256>>>(qp, kp, cs, sn);

    flash_fwd<<<dim3(SS / 64, NH, BB), 256, FLASH_SMEM_BYTES>>>(qp, kp, vp, yp);

    gemm_mma<<<dim3(HIDD / 128, M / 128), 256, GSMEM_BYTES>>>(yp, wo, out, M, HIDD, HIDD);
}

// round 7
// speedup vs baseline: 2.9060x; 1.6282x over previous
#include <cuda_runtime.h>
#include <cstdint>

// Problem constants (fixed shapes from reference)
#define BB   2
#define SS   2048
#define HIDD 2048
#define NH   16
#define NKV  4
#define HD   128
#define KVD  (NKV * HD)   // 512

// Scratch (allocation-free rule: __device__ globals)
__device__ float g_q[BB * SS * HIDD];    // [B,S,H,HD]
__device__ float g_k[BB * SS * KVD];     // [B,S,KVH,HD]
__device__ float g_v[BB * SS * KVD];     // [B,S,KVH,HD]
__device__ float g_y[BB * SS * HIDD];    // [B,S,HID] (tf32-rounded by flash)
__device__ float g_xc[BB * SS * HIDD];   // tf32-rounded x
__device__ float g_wq[HIDD * HIDD];      // tf32-rounded weights
__device__ float g_wk[KVD * HIDD];
__device__ float g_wv[KVD * HIDD];
__device__ float g_wo[HIDD * HIDD];

// ---- misc helpers ----
__device__ __forceinline__ uint32_t smem_u32(const void* p) {
    uint32_t a;
    asm("{ .reg .u64 t; cvta.to.shared.u64 t, %1; cvt.u32.u64 %0, t; }"
        : "=r"(a) : "l"(p));
    return a;
}
__device__ __forceinline__ uint32_t f2tf32(float f) {
    uint32_t t; asm("cvt.rna.tf32.f32 %0, %1;" : "=r"(t) : "f"(f)); return t;
}
__device__ __forceinline__ void cp_async16(uint32_t dst, const void* src) {
    asm volatile("cp.async.cg.shared.global [%0], [%1], 16;" :: "r"(dst), "l"(src));
}
#define CP_COMMIT() asm volatile("cp.async.commit_group;" ::: "memory")
#define CP_WAIT2()  asm volatile("cp.async.wait_group 2;" ::: "memory")

// mma.sync tf32 m16n8k8 (base sm_80+ PTX -> HMMA on sm_103)
__device__ __forceinline__ void mma_tf32(float* c, const uint32_t* a, const uint32_t* b) {
    asm volatile(
        "mma.sync.aligned.m16n8k8.row.col.f32.tf32.tf32.f32 "
        "{%0,%1,%2,%3}, {%4,%5,%6,%7}, {%8,%9}, {%0,%1,%2,%3};"
        : "+f"(c[0]), "+f"(c[1]), "+f"(c[2]), "+f"(c[3])
        : "r"(a[0]), "r"(a[1]), "r"(a[2]), "r"(a[3]), "r"(b[0]), "r"(b[1]));
}

// ============================================================================
// Elementwise tf32 rounding (RN): out[i] = tf32(in[i]); n % 4 == 0
// ============================================================================
__global__ void tf32_cvt(const float* __restrict__ in, float* __restrict__ out, int n)
{
    int i = (blockIdx.x * blockDim.x + threadIdx.x) * 4;
    if (i >= n) return;
    float4 v = *(const float4*)(in + i);
    uint4 o;
    o.x = f2tf32(v.x); o.y = f2tf32(v.y); o.z = f2tf32(v.z); o.w = f2tf32(v.w);
    *(uint4*)(out + i) = o;
}

// ============================================================================
// TF32 mma.sync GEMM:  C[M,N] = A[M,K] @ B[N,K]^T  (row-major; M,N%128, K%16)
// (unchanged from R6 — 128x128 CTA tile, 8 warps 32x64, 4-stage cp.async)
// ============================================================================
#define GSTAGE_FLOATS 5120
#define GSMEM_BYTES  (4 * GSTAGE_FLOATS * 4)

__device__ __forceinline__ void gemm_load_stage(
    uint32_t sbase, const float* __restrict__ Ag, const float* __restrict__ Bg,
    int K, int kt, int tid)
{
    int row = tid >> 1;
    int half = (tid & 1) * 8;
    const float* sa = Ag + (size_t)row * K + kt * 16 + half;
    const float* sb = Bg + (size_t)row * K + kt * 16 + half;
    uint32_t da = sbase + (row * 20 + half) * 4;
    uint32_t db = sbase + (2560 + row * 20 + half) * 4;
    cp_async16(da, sa);       cp_async16(da + 16, sa + 4);
    cp_async16(db, sb);       cp_async16(db + 16, sb + 4);
}

__global__ __launch_bounds__(256) void gemm_mma(
    const float* __restrict__ A, const float* __restrict__ B,
    float* __restrict__ C, int M, int N, int K)
{
    extern __shared__ __align__(16) float sm[];
    int tid = threadIdx.x;
    int lane = tid & 31, wid = tid >> 5;
    int gid = lane >> 2, tig = lane & 3;
    int wm = wid & 3, wn = wid >> 2;
    int m0 = blockIdx.y * 128, n0 = blockIdx.x * 128;

    const float* Ag = A + (size_t)m0 * K;
    const float* Bg = B + (size_t)n0 * K;
    uint32_t sb0 = smem_u32(sm);
    int nk = K / 16;

    float acc[2][8][4];
    #pragma unroll
    for (int i = 0; i < 2; i++)
        #pragma unroll
        for (int j = 0; j < 8; j++)
            #pragma unroll
            for (int r = 0; r < 4; r++) acc[i][j][r] = 0.f;

    #pragma unroll
    for (int s = 0; s < 3; s++) {
        gemm_load_stage(sb0 + s * GSTAGE_FLOATS * 4, Ag, Bg, K, s, tid);
        CP_COMMIT();
    }

    for (int s = 0; s < nk; s++) {
        CP_WAIT2();
        __syncthreads();
        if (s + 3 < nk)
            gemm_load_stage(sb0 + ((s + 3) & 3) * GSTAGE_FLOATS * 4, Ag, Bg, K, s + 3, tid);
        CP_COMMIT();

        const float* Asf = sm + (s & 3) * GSTAGE_FLOATS;
        const float* Bsf = Asf + 2560;

        #pragma unroll
        for (int ks = 0; ks < 2; ks++) {
            int kb = ks * 8;
            uint32_t af[2][4], bf[8][2];
            #pragma unroll
            for (int mt = 0; mt < 2; mt++) {
                int r = wm * 32 + mt * 16 + gid;
                af[mt][0] = __float_as_uint(Asf[r * 20 + kb + tig]);
                af[mt][1] = __float_as_uint(Asf[(r + 8) * 20 + kb + tig]);
                af[mt][2] = __float_as_uint(Asf[r * 20 + kb + tig + 4]);
                af[mt][3] = __float_as_uint(Asf[(r + 8) * 20 + kb + tig + 4]);
            }
            #pragma unroll
            for (int nt = 0; nt < 8; nt++) {
                int nn = wn * 64 + nt * 8 + gid;
                bf[nt][0] = __float_as_uint(Bsf[nn * 20 + kb + tig]);
                bf[nt][1] = __float_as_uint(Bsf[nn * 20 + kb + tig + 4]);
            }
            #pragma unroll
            for (int mt = 0; mt < 2; mt++)
                #pragma unroll
                for (int nt = 0; nt < 8; nt++)
                    mma_tf32(acc[mt][nt], af[mt], bf[nt]);
        }
        __syncthreads();
    }

    #pragma unroll
    for (int mt = 0; mt < 2; mt++) {
        int r = m0 + wm * 32 + mt * 16 + gid;
        #pragma unroll
        for (int nt = 0; nt < 8; nt++) {
            int cc = n0 + wn * 64 + nt * 8 + 2 * tig;
            *(float2*)&C[(size_t)r * N + cc]       = make_float2(acc[mt][nt][0], acc[mt][nt][1]);
            *(float2*)&C[(size_t)(r + 8) * N + cc] = make_float2(acc[mt][nt][2], acc[mt][nt][3]);
        }
    }
}

// ============================================================================
// RoPE applied in-place to Q [B,S,H,HD] and K [B,S,KVH,HD]
// ============================================================================
__global__ void rope_kernel(float* __restrict__ q, float* __restrict__ k,
                            const float* __restrict__ cs, const float* __restrict__ sn)
{
    int idx = blockIdx.x * blockDim.x + threadIdx.x;
    int i = idx & 63;
    int rest = idx >> 6;
    int hh = rest % (NH + NKV);
    rest /= (NH + NKV);
    int s = rest % SS;
    int b = rest / SS;

    float c = cs[s * 64 + i];
    float sv = sn[s * 64 + i];
    float* p;
    if (hh < NH) p = q + ((b * SS + s) * NH + hh) * HD + 2 * i;
    else         p = k + ((b * SS + s) * NKV + (hh - NH)) * HD + 2 * i;
    float e = p[0], o = p[1];
    p[0] = e * c - o * sv;
    p[1] = e * sv + o * c;
}

// ============================================================================
// Causal flash attention on mma.sync tf32.
// BQ=128, BK=64, HD=128. 256 threads = 8 warps; warp w owns q-rows w*16..+15.
// Q/K smem stride 132 (132%32==4 -> a/b frag LDS conflict-free via 4*gid+tig).
// V smem stride 136 (136%32==8 -> PV b-frag conflict-free via 8*tig+gid).
// Softmax row-reductions are tig-group shfls only (warp owns full rows).
// ============================================================================
#define FQS 132
#define FVS 136
#define FPS 68
#define FL_QS_OFF 0
#define FL_KS_OFF (128 * FQS)                       // 16896
#define FL_VS_OFF (FL_KS_OFF + 64 * FQS)            // 25344
#define FL_PS_OFF (FL_VS_OFF + 64 * FVS)            // 34048
#define FLASH_SMEM_BYTES ((FL_PS_OFF + 128 * FPS) * 4)   // 171008

__global__ __launch_bounds__(256, 1) void flash_mma(
    const float* __restrict__ Q, const float* __restrict__ K,
    const float* __restrict__ V, float* __restrict__ Y)
{
    extern __shared__ __align__(16) float sm[];
    float* Qs = sm + FL_QS_OFF;
    float* Ks = sm + FL_KS_OFF;
    float* Vs = sm + FL_VS_OFF;
    float* Ps = sm + FL_PS_OFF;

    int tid = threadIdx.x, lane = tid & 31, wid = tid >> 5;
    int gid = lane >> 2, tig = lane & 3;
    int qb = gridDim.x - 1 - blockIdx.x;     // heavy tiles first (causal balance)
    int h = blockIdx.y, b = blockIdx.z;
    int kvh = h >> 2;
    int q0 = qb * 128;
    int rbase = wid * 16 + gid;

    // Load Q tile (128 x 128), tf32-round into smem
    const float* Qg = Q + ((size_t)(b * SS + q0) * NH + h) * HD;
    #pragma unroll
    for (int it = 0; it < 16; it++) {
        int chunk = tid + it * 256;
        int r = chunk >> 5, c4 = (chunk & 31) * 4;
        float4 v = *(const float4*)(Qg + (size_t)r * (NH * HD) + c4);
        uint4 o = make_uint4(f2tf32(v.x), f2tf32(v.y), f2tf32(v.z), f2tf32(v.w));
        *(uint4*)&Qs[r * FQS + c4] = o;
    }

    float of[16][4];
    #pragma unroll
    for (int nt = 0; nt < 16; nt++)
        #pragma unroll
        for (int r = 0; r < 4; r++) of[nt][r] = 0.f;
    float m_i[2] = {-1e30f, -1e30f}, l_i[2] = {0.f, 0.f};
    const float scale = 0.088388347648318447f;   // 1/sqrt(128)

    int ktiles = 2 * qb + 2;
    for (int kt = 0; kt < ktiles; kt++) {
        int k0 = kt * 64;
        const float* Kg = K + ((size_t)(b * SS + k0) * NKV + kvh) * HD;
        const float* Vg = V + ((size_t)(b * SS + k0) * NKV + kvh) * HD;

        __syncthreads();   // prev PV done with Ks/Vs; Q visible after first pass
        #pragma unroll
        for (int it = 0; it < 8; it++) {
            int chunk = tid + it * 256;
            int r = chunk >> 5, c4 = (chunk & 31) * 4;
            float4 kv = *(const float4*)(Kg + (size_t)r * (NKV * HD) + c4);
            *(uint4*)&Ks[r * FQS + c4] =
                make_uint4(f2tf32(kv.x), f2tf32(kv.y), f2tf32(kv.z), f2tf32(kv.w));
            float4 vv = *(const float4*)(Vg + (size_t)r * (NKV * HD) + c4);
            *(uint4*)&Vs[r * FVS + c4] =
                make_uint4(f2tf32(vv.x), f2tf32(vv.y), f2tf32(vv.z), f2tf32(vv.w));
        }
        __syncthreads();

        // ---- S = Q K^T : warp tile 16 x 64 ----
        float sf[8][4];
        #pragma unroll
        for (int nt = 0; nt < 8; nt++)
            #pragma unroll
            for (int r = 0; r < 4; r++) sf[nt][r] = 0.f;

        #pragma unroll
        for (int kb = 0; kb < 16; kb++) {
            uint32_t af[4];
            const float* qr = Qs + rbase * FQS + kb * 8 + tig;
            af[0] = __float_as_uint(qr[0]);
            af[1] = __float_as_uint(qr[8 * FQS]);
            af[2] = __float_as_uint(qr[4]);
            af[3] = __float_as_uint(qr[8 * FQS + 4]);
            #pragma unroll
            for (int nt = 0; nt < 8; nt++) {
                uint32_t bf[2];
                const float* kr = Ks + (nt * 8 + gid) * FQS + kb * 8 + tig;
                bf[0] = __float_as_uint(kr[0]);
                bf[1] = __float_as_uint(kr[4]);
                mma_tf32(sf[nt], af, bf);
            }
        }

        // ---- online softmax (rows fully warp-owned; tig-group shfl) ----
        bool need_mask = (kt >= 2 * qb);
        #pragma unroll
        for (int i = 0; i < 2; i++) {
            int grow = q0 + rbase + i * 8;
            float vmax = -1e30f;
            #pragma unroll
            for (int nt = 0; nt < 8; nt++) {
                float v0 = sf[nt][i * 2 + 0] * scale;
                float v1 = sf[nt][i * 2 + 1] * scale;
                if (need_mask) {
                    int c0 = k0 + nt * 8 + 2 * tig;
                    if (c0 > grow)     v0 = -1e30f;
                    if (c0 + 1 > grow) v1 = -1e30f;
                }
                sf[nt][i * 2 + 0] = v0;
                sf[nt][i * 2 + 1] = v1;
                vmax = fmaxf(vmax, fmaxf(v0, v1));
            }
            vmax = fmaxf(vmax, __shfl_xor_sync(0xffffffffu, vmax, 1));
            vmax = fmaxf(vmax, __shfl_xor_sync(0xffffffffu, vmax, 2));
            float mn = fmaxf(m_i[i], vmax);
            float al = __expf(m_i[i] - mn);
            m_i[i] = mn;
            float rs = 0.f;
            #pragma unroll
            for (int nt = 0; nt < 8; nt++) {
                float e0 = __expf(sf[nt][i * 2 + 0] - mn);
                float e1 = __expf(sf[nt][i * 2 + 1] - mn);
                rs += e0 + e1;
                float2 pw;
                pw.x = __uint_as_float(f2tf32(e0));
                pw.y = __uint_as_float(f2tf32(e1));
                *(float2*)&Ps[(rbase + i * 8) * FPS + nt * 8 + 2 * tig] = pw;
            }
            rs += __shfl_xor_sync(0xffffffffu, rs, 1);
            rs += __shfl_xor_sync(0xffffffffu, rs, 2);
            l_i[i] = l_i[i] * al + rs;
            #pragma unroll
            for (int nt = 0; nt < 16; nt++) {
                of[nt][i * 2 + 0] *= al;
                of[nt][i * 2 + 1] *= al;
            }
        }
        __syncwarp();

        // ---- O += P V : warp tile 16 x 128 ----
        #pragma unroll
        for (int kb = 0; kb < 8; kb++) {
            uint32_t af[4];
            const float* pr = Ps + rbase * FPS + kb * 8 + tig;
            af[0] = __float_as_uint(pr[0]);
            af[1] = __float_as_uint(pr[8 * FPS]);
            af[2] = __float_as_uint(pr[4]);
            af[3] = __float_as_uint(pr[8 * FPS + 4]);
            #pragma unroll
            for (int nt = 0; nt < 16; nt++) {
                uint32_t bf[2];
                const float* vr = Vs + (kb * 8 + tig) * FVS + nt * 8 + gid;
                bf[0] = __float_as_uint(vr[0]);
                bf[1] = __float_as_uint(vr[4 * FVS]);
                mma_tf32(of[nt], af, bf);
            }
        }
    }

    // ---- epilogue: Y = O / l (tf32-rounded; feeds Wo gemm) ----
    float* Yg = Y + (size_t)(b * SS + q0) * HIDD + h * HD;
    #pragma unroll
    for (int i = 0; i < 2; i++) {
        float inv = 1.0f / l_i[i];
        int r = rbase + i * 8;
        #pragma unroll
        for (int nt = 0; nt < 16; nt++) {
            float2 w;
            w.x = __uint_as_float(f2tf32(of[nt][i * 2 + 0] * inv));
            w.y = __uint_as_float(f2tf32(of[nt][i * 2 + 1] * inv));
            *(float2*)&Yg[(size_t)r * HIDD + nt * 8 + 2 * tig] = w;
        }
    }
}

// ============================================================================
// Launch
// ============================================================================
extern "C" void kernel_launch(void* const* d_in, const int* in_sizes, int n_in,
                              void* d_out, int out_size)
{
    const float* x  = (const float*)d_in[0];
    const float* cs = (const float*)d_in[1];
    const float* sn = (const float*)d_in[2];
    const float* Wq = (const float*)d_in[3];
    const float* Wk = (const float*)d_in[4];
    const float* Wv = (const float*)d_in[5];
    const float* Wo = (const float*)d_in[6];
    float* out = (float*)d_out;

    float *qp, *kp, *vp, *yp, *xc, *wq, *wk, *wv, *wo;
    cudaGetSymbolAddress((void**)&qp, g_q);
    cudaGetSymbolAddress((void**)&kp, g_k);
    cudaGetSymbolAddress((void**)&vp, g_v);
    cudaGetSymbolAddress((void**)&yp, g_y);
    cudaGetSymbolAddress((void**)&xc, g_xc);
    cudaGetSymbolAddress((void**)&wq, g_wq);
    cudaGetSymbolAddress((void**)&wk, g_wk);
    cudaGetSymbolAddress((void**)&wv, g_wv);
    cudaGetSymbolAddress((void**)&wo, g_wo);

    const int M = BB * SS;   // 4096

    cudaFuncSetAttribute(gemm_mma, cudaFuncAttributeMaxDynamicSharedMemorySize, GSMEM_BYTES);
    cudaFuncSetAttribute(flash_mma, cudaFuncAttributeMaxDynamicSharedMemorySize, FLASH_SMEM_BYTES);

    // one-shot tf32 rounding of GEMM operands
    tf32_cvt<<<(M * HIDD / 4 + 255) / 256, 256>>>(x, xc, M * HIDD);
    tf32_cvt<<<(HIDD * HIDD / 4 + 255) / 256, 256>>>(Wq, wq, HIDD * HIDD);
    tf32_cvt<<<(KVD * HIDD / 4 + 255) / 256, 256>>>(Wk, wk, KVD * HIDD);
    tf32_cvt<<<(KVD * HIDD / 4 + 255) / 256, 256>>>(Wv, wv, KVD * HIDD);
    tf32_cvt<<<(HIDD * HIDD / 4 + 255) / 256, 256>>>(Wo, wo, HIDD * HIDD);

    gemm_mma<<<dim3(HIDD / 128, M / 128), 256, GSMEM_BYTES>>>(xc, wq, qp, M, HIDD, HIDD);
    gemm_mma<<<dim3(KVD  / 128, M / 128), 256, GSMEM_BYTES>>>(xc, wk, kp, M, KVD,  HIDD);
    gemm_mma<<<dim3(KVD  / 128, M / 128), 256, GSMEM_BYTES>>>(xc, wv, vp, M, KVD,  HIDD);

    rope_kernel<<<(BB * SS * (NH + NKV) * (HD / 2)) / 256, 256>>>(qp, kp, cs, sn);

    flash_mma<<<dim3(SS / 128, NH, BB), 256, FLASH_SMEM_BYTES>>>(qp, kp, vp, yp);

    gemm_mma<<<dim3(HIDD / 128, M / 128), 256, GSMEM_BYTES>>>(yp, wo, out, M, HIDD, HIDD);
}

// round 11
// speedup vs baseline: 5.2812x; 1.8173x over previous
#include <cuda_runtime.h>
#include <cuda_fp16.h>
#include <cstdint>

// Problem constants (fixed shapes from reference)
#define BB   2
#define SS   2048
#define HIDD 2048
#define NH   16
#define NKV  4
#define HD   128
#define KVD  (NKV * HD)   // 512

// Scratch (allocation-free rule: __device__ globals), fp16 pipeline
__device__ __half g_xh[BB * SS * HIDD];
__device__ __half g_wqh[HIDD * HIDD];
__device__ __half g_wkh[KVD * HIDD];
__device__ __half g_wvh[KVD * HIDD];
__device__ __half g_woh[HIDD * HIDD];
__device__ __half g_qh[BB * SS * HIDD];   // [B,S,H,HD]
__device__ __half g_kh[BB * SS * KVD];    // [B,S,KVH,HD]
__device__ __half g_vh[BB * SS * KVD];    // [B,S,KVH,HD]
__device__ __half g_yh[BB * SS * HIDD];   // [B,S,HID]

// ---- helpers ----
__device__ __forceinline__ uint32_t smem_u32(const void* p) {
    uint32_t a;
    asm("{ .reg .u64 t; cvta.to.shared.u64 t, %1; cvt.u32.u64 %0, t; }"
        : "=r"(a) : "l"(p));
    return a;
}
__device__ __forceinline__ void cp_async16(uint32_t dst, const void* src) {
    asm volatile("cp.async.cg.shared.global [%0], [%1], 16;" :: "r"(dst), "l"(src));
}
#define CP_COMMIT() asm volatile("cp.async.commit_group;" ::: "memory")
#define CP_WAIT2()  asm volatile("cp.async.wait_group 2;" ::: "memory")

// mma.sync fp16 m16n8k16, fp32 accumulate (base sm_80+ PTX)
__device__ __forceinline__ void mma_f16(float* c, const uint32_t* a, const uint32_t* b) {
    asm volatile(
        "mma.sync.aligned.m16n8k16.row.col.f32.f16.f16.f32 "
        "{%0,%1,%2,%3}, {%4,%5,%6,%7}, {%8,%9}, {%0,%1,%2,%3};"
        : "+f"(c[0]), "+f"(c[1]), "+f"(c[2]), "+f"(c[3])
        : "r"(a[0]), "r"(a[1]), "r"(a[2]), "r"(a[3]), "r"(b[0]), "r"(b[1]));
}
// ldmatrix x4 transposed b16 (base sm_75+ PTX)
__device__ __forceinline__ void ldsm_x4_trans(uint32_t* r, uint32_t addr) {
    asm volatile(
        "ldmatrix.sync.aligned.m8n8.x4.trans.shared.b16 {%0,%1,%2,%3}, [%4];"
        : "=r"(r[0]), "=r"(r[1]), "=r"(r[2]), "=r"(r[3]) : "r"(addr));
}

// ============================================================================
// Elementwise f32 -> f16 (RN); n % 8 == 0
// ============================================================================
__global__ void f2h_cvt(const float* __restrict__ in, __half* __restrict__ out, int n)
{
    int i = (blockIdx.x * blockDim.x + threadIdx.x) * 8;
    if (i >= n) return;
    float4 a = *(const float4*)(in + i);
    float4 b = *(const float4*)(in + i + 4);
    __half2 h0 = __float22half2_rn(make_float2(a.x, a.y));
    __half2 h1 = __float22half2_rn(make_float2(a.z, a.w));
    __half2 h2 = __float22half2_rn(make_float2(b.x, b.y));
    __half2 h3 = __float22half2_rn(make_float2(b.z, b.w));
    uint4 o = make_uint4(*(uint32_t*)&h0, *(uint32_t*)&h1, *(uint32_t*)&h2, *(uint32_t*)&h3);
    *(uint4*)(out + i) = o;
}

// ============================================================================
// FP16 mma GEMM:  C[M,N] = A[M,K] @ B[N,K]^T  (row-major; M,N%128, K%32)
// 128x128 CTA tile, 8 warps of 32x64, K-chunk 32 halves, 4-stage cp.async ring.
// Smem row stride 40 halves (20 words %32 == 4 -> conflict-free frag LDS).
// out_half: C stored as __half (QKV gemms) or float (output projection).
// ============================================================================
#define GH_STAGE_BYTES 20480                 // (128+128) rows * 40 halves * 2B
#define GH_SMEM (4 * GH_STAGE_BYTES)         // 81920

__device__ __forceinline__ void gemm_load_h(
    uint32_t sbase, const __half* __restrict__ Ag, const __half* __restrict__ Bg,
    int K, int kt, int tid)
{
    int row = tid >> 1;
    int c = (tid & 1) * 16;                  // half offset within the 32-half chunk
    const __half* sa = Ag + (size_t)row * K + kt * 32 + c;
    const __half* sb = Bg + (size_t)row * K + kt * 32 + c;
    uint32_t da = sbase + (row * 40 + c) * 2;
    uint32_t db = sbase + (128 * 40 + row * 40 + c) * 2;
    cp_async16(da, sa);       cp_async16(da + 16, sa + 8);
    cp_async16(db, sb);       cp_async16(db + 16, sb + 8);
}

__global__ __launch_bounds__(256, 2) void gemm_h(
    const __half* __restrict__ A, const __half* __restrict__ B,
    void* __restrict__ Cv, int M, int N, int K, int out_half)
{
    extern __shared__ __align__(16) char smc[];
    int tid = threadIdx.x;
    int lane = tid & 31, wid = tid >> 5;
    int gid = lane >> 2, tig = lane & 3;
    int wm = wid & 3, wn = wid >> 2;
    int m0 = blockIdx.y * 128, n0 = blockIdx.x * 128;

    const __half* Ag = A + (size_t)m0 * K;
    const __half* Bg = B + (size_t)n0 * K;
    uint32_t sb0 = smem_u32(smc);
    int nk = K / 32;

    float acc[2][8][4];
    #pragma unroll
    for (int i = 0; i < 2; i++)
        #pragma unroll
        for (int j = 0; j < 8; j++)
            #pragma unroll
            for (int r = 0; r < 4; r++) acc[i][j][r] = 0.f;

    #pragma unroll
    for (int s = 0; s < 3; s++) {
        gemm_load_h(sb0 + s * GH_STAGE_BYTES, Ag, Bg, K, s, tid);
        CP_COMMIT();
    }

    for (int s = 0; s < nk; s++) {
        CP_WAIT2();
        __syncthreads();
        if (s + 3 < nk)
            gemm_load_h(sb0 + ((s + 3) & 3) * GH_STAGE_BYTES, Ag, Bg, K, s + 3, tid);
        CP_COMMIT();

        const char* Asf = smc + (s & 3) * GH_STAGE_BYTES;
        const char* Bsf = Asf + 128 * 80;

        #pragma unroll
        for (int ks = 0; ks < 2; ks++) {
            int kb2 = ks * 32;                      // byte offset of k16 block
            uint32_t af[2][4], bf[8][2];
            #pragma unroll
            for (int mt = 0; mt < 2; mt++) {
                const char* ar = Asf + (wm * 32 + mt * 16 + gid) * 80 + kb2 + tig * 4;
                af[mt][0] = *(const uint32_t*)ar;
                af[mt][1] = *(const uint32_t*)(ar + 8 * 80);
                af[mt][2] = *(const uint32_t*)(ar + 16);
                af[mt][3] = *(const uint32_t*)(ar + 8 * 80 + 16);
            }
            #pragma unroll
            for (int nt = 0; nt < 8; nt++) {
                const char* br = Bsf + (wn * 64 + nt * 8 + gid) * 80 + kb2 + tig * 4;
                bf[nt][0] = *(const uint32_t*)br;
                bf[nt][1] = *(const uint32_t*)(br + 16);
            }
            #pragma unroll
            for (int mt = 0; mt < 2; mt++)
                #pragma unroll
                for (int nt = 0; nt < 8; nt++)
                    mma_f16(acc[mt][nt], af[mt], bf[nt]);
        }
        __syncthreads();
    }

    if (out_half) {
        __half* C = (__half*)Cv;
        #pragma unroll
        for (int mt = 0; mt < 2; mt++) {
            int r = m0 + wm * 32 + mt * 16 + gid;
            #pragma unroll
            for (int nt = 0; nt < 8; nt++) {
                int cc = n0 + wn * 64 + nt * 8 + 2 * tig;
                *(__half2*)&C[(size_t)r * N + cc] =
                    __float22half2_rn(make_float2(acc[mt][nt][0], acc[mt][nt][1]));
                *(__half2*)&C[(size_t)(r + 8) * N + cc] =
                    __float22half2_rn(make_float2(acc[mt][nt][2], acc[mt][nt][3]));
            }
        }
    } else {
        float* C = (float*)Cv;
        #pragma unroll
        for (int mt = 0; mt < 2; mt++) {
            int r = m0 + wm * 32 + mt * 16 + gid;
            #pragma unroll
            for (int nt = 0; nt < 8; nt++) {
                int cc = n0 + wn * 64 + nt * 8 + 2 * tig;
                *(float2*)&C[(size_t)r * N + cc]       = make_float2(acc[mt][nt][0], acc[mt][nt][1]);
                *(float2*)&C[(size_t)(r + 8) * N + cc] = make_float2(acc[mt][nt][2], acc[mt][nt][3]);
            }
        }
    }
}

// ============================================================================
// RoPE in-place on fp16 Q [B,S,H,HD] and K [B,S,KVH,HD] (fp32 math)
// ============================================================================
__global__ void rope_h(__half* __restrict__ q, __half* __restrict__ k,
                       const float* __restrict__ cs, const float* __restrict__ sn)
{
    int idx = blockIdx.x * blockDim.x + threadIdx.x;
    int i = idx & 63;
    int rest = idx >> 6;
    int hh = rest % (NH + NKV);
    rest /= (NH + NKV);
    int s = rest % SS;
    int b = rest / SS;

    float c = cs[s * 64 + i];
    float sv = sn[s * 64 + i];
    __half* p;
    if (hh < NH) p = q + ((size_t)(b * SS + s) * NH + hh) * HD + 2 * i;
    else         p = k + ((size_t)(b * SS + s) * NKV + (hh - NH)) * HD + 2 * i;
    float2 f = __half22float2(*(__half2*)p);
    *(__half2*)p = __float22half2_rn(make_float2(f.x * c - f.y * sv, f.x * sv + f.y * c));
}

// ============================================================================
// Causal flash attention on mma.sync fp16 (fp32 softmax + accumulators).
// BQ=128, BK=64, HD=128. 8 warps; warp w owns q-rows w*16..w*16+15.
// Q/K/V smem stride 136 halves (68w %32==4 -> conflict-free), P stride 72.
// V b-frags via ldmatrix.x4.trans (no transpose pass).
// ============================================================================
#define HQS 136
#define HPS 72
#define FH_KS_OFF (128 * HQS)                 // 17408 halves
#define FH_VS_OFF (FH_KS_OFF + 64 * HQS)      // 26112
#define FH_PS_OFF (FH_VS_OFF + 64 * HQS)      // 34816
#define FLASH_H_BYTES ((FH_PS_OFF + 128 * HPS) * 2)    // 88064

__global__ __launch_bounds__(256, 2) void flash_h(
    const __half* __restrict__ Q, const __half* __restrict__ K,
    const __half* __restrict__ V, __half* __restrict__ Y)
{
    extern __shared__ __align__(16) __half hsm[];
    __half* Qs = hsm;
    __half* Ks = hsm + FH_KS_OFF;
    __half* Vs = hsm + FH_VS_OFF;
    __half* Ps = hsm + FH_PS_OFF;
    uint32_t vs_base = smem_u32(Vs);

    int tid = threadIdx.x, lane = tid & 31, wid = tid >> 5;
    int gid = lane >> 2, tig = lane & 3;
    int qb = gridDim.x - 1 - blockIdx.x;      // heavy tiles first
    int h = blockIdx.y, b = blockIdx.z;
    int kvh = h >> 2;
    int q0 = qb * 128;
    int rbase = wid * 16 + gid;

    // Load Q tile (128 x 128 halves): pure 16B copies
    const __half* Qg = Q + ((size_t)(b * SS + q0) * NH + h) * HD;
    #pragma unroll
    for (int it = 0; it < 8; it++) {
        int chunk = tid + it * 256;
        int r = chunk >> 4, c8 = (chunk & 15) * 8;
        *(uint4*)&Qs[r * HQS + c8] = *(const uint4*)(Qg + (size_t)r * (NH * HD) + c8);
    }

    float of[16][4];
    #pragma unroll
    for (int nt = 0; nt < 16; nt++)
        #pragma unroll
        for (int r = 0; r < 4; r++) of[nt][r] = 0.f;
    float m_i[2] = {-1e30f, -1e30f}, l_i[2] = {0.f, 0.f};
    const float scale = 0.088388347648318447f;   // 1/sqrt(128)

    int ktiles = 2 * qb + 2;
    for (int kt = 0; kt < ktiles; kt++) {
        int k0 = kt * 64;
        const __half* Kg = K + ((size_t)(b * SS + k0) * NKV + kvh) * HD;
        const __half* Vg = V + ((size_t)(b * SS + k0) * NKV + kvh) * HD;

        __syncthreads();
        #pragma unroll
        for (int it = 0; it < 4; it++) {
            int chunk = tid + it * 256;
            int r = chunk >> 4, c8 = (chunk & 15) * 8;
            *(uint4*)&Ks[r * HQS + c8] = *(const uint4*)(Kg + (size_t)r * KVD + c8);
            *(uint4*)&Vs[r * HQS + c8] = *(const uint4*)(Vg + (size_t)r * KVD + c8);
        }
        __syncthreads();

        // ---- S = Q K^T : warp tile 16 x 64, K-dim 128 = 8 k16 steps ----
        float sf[8][4];
        #pragma unroll
        for (int nt = 0; nt < 8; nt++)
            #pragma unroll
            for (int r = 0; r < 4; r++) sf[nt][r] = 0.f;

        #pragma unroll
        for (int kb = 0; kb < 8; kb++) {
            uint32_t af[4];
            const char* qr = (const char*)Qs + rbase * (HQS * 2) + kb * 32 + tig * 4;
            af[0] = *(const uint32_t*)qr;
            af[1] = *(const uint32_t*)(qr + 8 * HQS * 2);
            af[2] = *(const uint32_t*)(qr + 16);
            af[3] = *(const uint32_t*)(qr + 8 * HQS * 2 + 16);
            #pragma unroll
            for (int nt = 0; nt < 8; nt++) {
                uint32_t bf[2];
                const char* kr = (const char*)Ks + (nt * 8 + gid) * (HQS * 2) + kb * 32 + tig * 4;
                bf[0] = *(const uint32_t*)kr;
                bf[1] = *(const uint32_t*)(kr + 16);
                mma_f16(sf[nt], af, bf);
            }
        }

        // ---- online softmax (rows warp-owned; tig-group shfls) ----
        bool need_mask = (kt >= 2 * qb);
        #pragma unroll
        for (int i = 0; i < 2; i++) {
            int grow = q0 + rbase + i * 8;
            float vmax = -1e30f;
            #pragma unroll
            for (int nt = 0; nt < 8; nt++) {
                float v0 = sf[nt][i * 2 + 0] * scale;
                float v1 = sf[nt][i * 2 + 1] * scale;
                if (need_mask) {
                    int c0 = k0 + nt * 8 + 2 * tig;
                    if (c0 > grow)     v0 = -1e30f;
                    if (c0 + 1 > grow) v1 = -1e30f;
                }
                sf[nt][i * 2 + 0] = v0;
                sf[nt][i * 2 + 1] = v1;
                vmax = fmaxf(vmax, fmaxf(v0, v1));
            }
            vmax = fmaxf(vmax, __shfl_xor_sync(0xffffffffu, vmax, 1));
            vmax = fmaxf(vmax, __shfl_xor_sync(0xffffffffu, vmax, 2));
            float mn = fmaxf(m_i[i], vmax);
            float al = __expf(m_i[i] - mn);
            m_i[i] = mn;
            float rs = 0.f;
            #pragma unroll
            for (int nt = 0; nt < 8; nt++) {
                float e0 = __expf(sf[nt][i * 2 + 0] - mn);
                float e1 = __expf(sf[nt][i * 2 + 1] - mn);
                rs += e0 + e1;
                *(__half2*)((char*)Ps + (rbase + i * 8) * (HPS * 2) + (nt * 8 + 2 * tig) * 2)
                    = __float22half2_rn(make_float2(e0, e1));
            }
            rs += __shfl_xor_sync(0xffffffffu, rs, 1);
            rs += __shfl_xor_sync(0xffffffffu, rs, 2);
            l_i[i] = l_i[i] * al + rs;
            #pragma unroll
            for (int nt = 0; nt < 16; nt++) {
                of[nt][i * 2 + 0] *= al;
                of[nt][i * 2 + 1] *= al;
            }
        }
        __syncwarp();

        // ---- O += P V : k=64 -> 2 passes of 2 k16 steps; V via ldmatrix.trans ----
        #pragma unroll
        for (int pass = 0; pass < 2; pass++) {
            uint32_t pa[2][4];
            const char* pr = (const char*)Ps + rbase * (HPS * 2) + pass * 64 + tig * 4;
            #pragma unroll
            for (int ks = 0; ks < 2; ks++) {
                pa[ks][0] = *(const uint32_t*)(pr + ks * 32);
                pa[ks][1] = *(const uint32_t*)(pr + ks * 32 + 8 * HPS * 2);
                pa[ks][2] = *(const uint32_t*)(pr + ks * 32 + 16);
                pa[ks][3] = *(const uint32_t*)(pr + ks * 32 + 8 * HPS * 2 + 16);
            }
            uint32_t vrow = vs_base + (pass * 32 + lane) * (HQS * 2);
            #pragma unroll
            for (int nt = 0; nt < 16; nt++) {
                uint32_t vb[4];
                ldsm_x4_trans(vb, vrow + nt * 16);
                mma_f16(of[nt], pa[0], vb);
                mma_f16(of[nt], pa[1], vb + 2);
            }
        }
    }

    // ---- epilogue: Y = O / l (fp16 out; feeds Wo gemm) ----
    __half* Yg = Y + (size_t)(b * SS + q0) * HIDD + h * HD;
    #pragma unroll
    for (int i = 0; i < 2; i++) {
        float inv = 1.0f / l_i[i];
        int r = rbase + i * 8;
        #pragma unroll
        for (int nt = 0; nt < 16; nt++) {
            *(__half2*)&Yg[(size_t)r * HIDD + nt * 8 + 2 * tig] =
                __float22half2_rn(make_float2(of[nt][i * 2 + 0] * inv,
                                              of[nt][i * 2 + 1] * inv));
        }
    }
}

// ============================================================================
// Launch
// ============================================================================
extern "C" void kernel_launch(void* const* d_in, const int* in_sizes, int n_in,
                              void* d_out, int out_size)
{
    const float* x  = (const float*)d_in[0];
    const float* cs = (const float*)d_in[1];
    const float* sn = (const float*)d_in[2];
    const float* Wq = (const float*)d_in[3];
    const float* Wk = (const float*)d_in[4];
    const float* Wv = (const float*)d_in[5];
    const float* Wo = (const float*)d_in[6];
    float* out = (float*)d_out;

    __half *xh, *wqh, *wkh, *wvh, *woh, *qh, *kh, *vh, *yh;
    cudaGetSymbolAddress((void**)&xh,  g_xh);
    cudaGetSymbolAddress((void**)&wqh, g_wqh);
    cudaGetSymbolAddress((void**)&wkh, g_wkh);
    cudaGetSymbolAddress((void**)&wvh, g_wvh);
    cudaGetSymbolAddress((void**)&woh, g_woh);
    cudaGetSymbolAddress((void**)&qh,  g_qh);
    cudaGetSymbolAddress((void**)&kh,  g_kh);
    cudaGetSymbolAddress((void**)&vh,  g_vh);
    cudaGetSymbolAddress((void**)&yh,  g_yh);

    const int M = BB * SS;   // 4096

    cudaFuncSetAttribute(gemm_h,  cudaFuncAttributeMaxDynamicSharedMemorySize, GH_SMEM);
    cudaFuncSetAttribute(flash_h, cudaFuncAttributeMaxDynamicSharedMemorySize, FLASH_H_BYTES);

    // one-shot f32 -> f16 conversion of GEMM operands
    f2h_cvt<<<(M * HIDD / 8 + 255) / 256, 256>>>(x, xh, M * HIDD);
    f2h_cvt<<<(HIDD * HIDD / 8 + 255) / 256, 256>>>(Wq, wqh, HIDD * HIDD);
    f2h_cvt<<<(KVD * HIDD / 8 + 255) / 256, 256>>>(Wk, wkh, KVD * HIDD);
    f2h_cvt<<<(KVD * HIDD / 8 + 255) / 256, 256>>>(Wv, wvh, KVD * HIDD);
    f2h_cvt<<<(HIDD * HIDD / 8 + 255) / 256, 256>>>(Wo, woh, HIDD * HIDD);

    gemm_h<<<dim3(HIDD / 128, M / 128), 256, GH_SMEM>>>(xh, wqh, qh, M, HIDD, HIDD, 1);
    gemm_h<<<dim3(KVD  / 128, M / 128), 256, GH_SMEM>>>(xh, wkh, kh, M, KVD,  HIDD, 1);
    gemm_h<<<dim3(KVD  / 128, M / 128), 256, GH_SMEM>>>(xh, wvh, vh, M, KVD,  HIDD, 1);

    rope_h<<<(BB * SS * (NH + NKV) * (HD / 2)) / 256, 256>>>(qh, kh, cs, sn);

    flash_h<<<dim3(SS / 128, NH, BB), 256, FLASH_H_BYTES>>>(qh, kh, vh, yh);

    gemm_h<<<dim3(HIDD / 128, M / 128), 256, GH_SMEM>>>(yh, woh, out, M, HIDD, HIDD, 0);
}

// round 14
// speedup vs baseline: 5.5237x; 1.0459x over previous
#include <cuda_runtime.h>
#include <cuda_fp16.h>
#include <cstdint>

// Problem constants (fixed shapes from reference)
#define BB   2
#define SS   2048
#define HIDD 2048
#define NH   16
#define NKV  4
#define HD   128
#define KVD  (NKV * HD)   // 512
#define QKVN (HIDD + 2 * KVD)   // 3072 packed q|k|v columns

// Scratch (allocation-free rule: __device__ globals), fp16 pipeline
__device__ __half g_xh[BB * SS * HIDD];
__device__ __half g_wqkv[QKVN * HIDD];      // rows: Wq(2048) | Wk(512) | Wv(512)
__device__ __half g_woh[HIDD * HIDD];
__device__ __half g_qkv[BB * SS * QKVN];    // packed per-token q|k|v (rope applied)
__device__ __half g_yh[BB * SS * HIDD];     // attention output

// ---- helpers ----
__device__ __forceinline__ uint32_t smem_u32(const void* p) {
    uint32_t a;
    asm("{ .reg .u64 t; cvta.to.shared.u64 t, %1; cvt.u32.u64 %0, t; }"
        : "=r"(a) : "l"(p));
    return a;
}
__device__ __forceinline__ void cp_async16(uint32_t dst, const void* src) {
    asm volatile("cp.async.cg.shared.global [%0], [%1], 16;" :: "r"(dst), "l"(src));
}
#define CP_COMMIT() asm volatile("cp.async.commit_group;" ::: "memory")
#define CP_WAIT2()  asm volatile("cp.async.wait_group 2;" ::: "memory")

// mma.sync fp16 m16n8k16, fp32 accumulate (base sm_80+ PTX)
__device__ __forceinline__ void mma_f16(float* c, const uint32_t* a, const uint32_t* b) {
    asm volatile(
        "mma.sync.aligned.m16n8k16.row.col.f32.f16.f16.f32 "
        "{%0,%1,%2,%3}, {%4,%5,%6,%7}, {%8,%9}, {%0,%1,%2,%3};"
        : "+f"(c[0]), "+f"(c[1]), "+f"(c[2]), "+f"(c[3])
        : "r"(a[0]), "r"(a[1]), "r"(a[2]), "r"(a[3]), "r"(b[0]), "r"(b[1]));
}
// ldmatrix x4 transposed b16 (base sm_75+ PTX)
__device__ __forceinline__ void ldsm_x4_trans(uint32_t* r, uint32_t addr) {
    asm volatile(
        "ldmatrix.sync.aligned.m8n8.x4.trans.shared.b16 {%0,%1,%2,%3}, [%4];"
        : "=r"(r[0]), "=r"(r[1]), "=r"(r[2]), "=r"(r[3]) : "r"(addr));
}

// ============================================================================
// Elementwise f32 -> f16 (RN); n % 8 == 0
// ============================================================================
__global__ void f2h_cvt(const float* __restrict__ in, __half* __restrict__ out, int n)
{
    int i = (blockIdx.x * blockDim.x + threadIdx.x) * 8;
    if (i >= n) return;
    float4 a = *(const float4*)(in + i);
    float4 b = *(const float4*)(in + i + 4);
    __half2 h0 = __float22half2_rn(make_float2(a.x, a.y));
    __half2 h1 = __float22half2_rn(make_float2(a.z, a.w));
    __half2 h2 = __float22half2_rn(make_float2(b.x, b.y));
    __half2 h3 = __float22half2_rn(make_float2(b.z, b.w));
    uint4 o = make_uint4(*(uint32_t*)&h0, *(uint32_t*)&h1, *(uint32_t*)&h2, *(uint32_t*)&h3);
    *(uint4*)(out + i) = o;
}

// ============================================================================
// FP16 mma GEMM:  C[M,N] = A[M,K] @ B[N,K]^T  (row-major; M,N%128, K%32)
// 128x128 CTA tile, 8 warps of 32x64, K-chunk 32 halves, 4-stage cp.async ring.
// Smem row stride 40 halves (20 words %32==4 -> conflict-free frag LDS).
// Epilogue modes:
//   out_half=1: fp16 store; columns < rope_n get RoPE rotation using cs/sn
//               (pair = (2i, 2i+1) within a 128-col head; i = (col&127)>>1,
//                s = row & (SS-1)). rope_n=0 disables.
//   out_half=0: fp32 store (output projection).
// ============================================================================
#define GH_STAGE_BYTES 20480                 // (128+128) rows * 40 halves * 2B
#define GH_SMEM (4 * GH_STAGE_BYTES)         // 81920

__device__ __forceinline__ void gemm_load_h(
    uint32_t sbase, const __half* __restrict__ Ag, const __half* __restrict__ Bg,
    int K, int kt, int tid)
{
    int row = tid >> 1;
    int c = (tid & 1) * 16;
    const __half* sa = Ag + (size_t)row * K + kt * 32 + c;
    const __half* sb = Bg + (size_t)row * K + kt * 32 + c;
    uint32_t da = sbase + (row * 40 + c) * 2;
    uint32_t db = sbase + (128 * 40 + row * 40 + c) * 2;
    cp_async16(da, sa);       cp_async16(da + 16, sa + 8);
    cp_async16(db, sb);       cp_async16(db + 16, sb + 8);
}

__global__ __launch_bounds__(256, 2) void gemm_h(
    const __half* __restrict__ A, const __half* __restrict__ B,
    void* __restrict__ Cv, int M, int N, int K, int out_half,
    const float* __restrict__ cs, const float* __restrict__ sn, int rope_n)
{
    extern __shared__ __align__(16) char smc[];
    int tid = threadIdx.x;
    int lane = tid & 31, wid = tid >> 5;
    int gid = lane >> 2, tig = lane & 3;
    int wm = wid & 3, wn = wid >> 2;
    int m0 = blockIdx.y * 128, n0 = blockIdx.x * 128;

    const __half* Ag = A + (size_t)m0 * K;
    const __half* Bg = B + (size_t)n0 * K;
    uint32_t sb0 = smem_u32(smc);
    int nk = K / 32;

    float acc[2][8][4];
    #pragma unroll
    for (int i = 0; i < 2; i++)
        #pragma unroll
        for (int j = 0; j < 8; j++)
            #pragma unroll
            for (int r = 0; r < 4; r++) acc[i][j][r] = 0.f;

    #pragma unroll
    for (int s = 0; s < 3; s++) {
        gemm_load_h(sb0 + s * GH_STAGE_BYTES, Ag, Bg, K, s, tid);
        CP_COMMIT();
    }

    for (int s = 0; s < nk; s++) {
        CP_WAIT2();
        __syncthreads();
        if (s + 3 < nk)
            gemm_load_h(sb0 + ((s + 3) & 3) * GH_STAGE_BYTES, Ag, Bg, K, s + 3, tid);
        CP_COMMIT();

        const char* Asf = smc + (s & 3) * GH_STAGE_BYTES;
        const char* Bsf = Asf + 128 * 80;

        #pragma unroll
        for (int ks = 0; ks < 2; ks++) {
            int kb2 = ks * 32;
            uint32_t af[2][4], bf[8][2];
            #pragma unroll
            for (int mt = 0; mt < 2; mt++) {
                const char* ar = Asf + (wm * 32 + mt * 16 + gid) * 80 + kb2 + tig * 4;
                af[mt][0] = *(const uint32_t*)ar;
                af[mt][1] = *(const uint32_t*)(ar + 8 * 80);
                af[mt][2] = *(const uint32_t*)(ar + 16);
                af[mt][3] = *(const uint32_t*)(ar + 8 * 80 + 16);
            }
            #pragma unroll
            for (int nt = 0; nt < 8; nt++) {
                const char* br = Bsf + (wn * 64 + nt * 8 + gid) * 80 + kb2 + tig * 4;
                bf[nt][0] = *(const uint32_t*)br;
                bf[nt][1] = *(const uint32_t*)(br + 16);
            }
            #pragma unroll
            for (int mt = 0; mt < 2; mt++)
                #pragma unroll
                for (int nt = 0; nt < 8; nt++)
                    mma_f16(acc[mt][nt], af[mt], bf[nt]);
        }
        __syncthreads();
    }

    if (out_half) {
        __half* C = (__half*)Cv;
        #pragma unroll
        for (int mt = 0; mt < 2; mt++) {
            int r0 = m0 + wm * 32 + mt * 16 + gid;
            int s0 = r0 & (SS - 1), s1 = (r0 + 8) & (SS - 1);
            #pragma unroll
            for (int nt = 0; nt < 8; nt++) {
                int cc = n0 + wn * 64 + nt * 8 + 2 * tig;
                float2 p0 = make_float2(acc[mt][nt][0], acc[mt][nt][1]);
                float2 p1 = make_float2(acc[mt][nt][2], acc[mt][nt][3]);
                if (cc < rope_n) {
                    int i = (cc & 127) >> 1;
                    float c0 = cs[s0 * 64 + i], v0 = sn[s0 * 64 + i];
                    float c1 = cs[s1 * 64 + i], v1 = sn[s1 * 64 + i];
                    p0 = make_float2(p0.x * c0 - p0.y * v0, p0.x * v0 + p0.y * c0);
                    p1 = make_float2(p1.x * c1 - p1.y * v1, p1.x * v1 + p1.y * c1);
                }
                *(__half2*)&C[(size_t)r0 * N + cc]       = __float22half2_rn(p0);
                *(__half2*)&C[(size_t)(r0 + 8) * N + cc] = __float22half2_rn(p1);
            }
        }
    } else {
        float* C = (float*)Cv;
        #pragma unroll
        for (int mt = 0; mt < 2; mt++) {
            int r = m0 + wm * 32 + mt * 16 + gid;
            #pragma unroll
            for (int nt = 0; nt < 8; nt++) {
                int cc = n0 + wn * 64 + nt * 8 + 2 * tig;
                *(float2*)&C[(size_t)r * N + cc]       = make_float2(acc[mt][nt][0], acc[mt][nt][1]);
                *(float2*)&C[(size_t)(r + 8) * N + cc] = make_float2(acc[mt][nt][2], acc[mt][nt][3]);
            }
        }
    }
}

// ============================================================================
// Causal flash attention on mma.sync fp16 (fp32 softmax + accumulators).
// Reads packed qkv buffer: row stride QKVN; q at col h*128, k at 2048+kvh*128,
// v at 2560+kvh*128. BQ=128, BK=64, HD=128, 8 warps (warp owns 16 q-rows).
// Q/K/V smem stride 136 halves, P stride 72 (both %32==4 words -> no conflicts).
// ============================================================================
#define HQS 136
#define HPS 72
#define FH_KS_OFF (128 * HQS)
#define FH_VS_OFF (FH_KS_OFF + 64 * HQS)
#define FH_PS_OFF (FH_VS_OFF + 64 * HQS)
#define FLASH_H_BYTES ((FH_PS_OFF + 128 * HPS) * 2)    // 88064

__global__ __launch_bounds__(256, 2) void flash_h(
    const __half* __restrict__ QKV, __half* __restrict__ Y)
{
    extern __shared__ __align__(16) __half hsm[];
    __half* Qs = hsm;
    __half* Ks = hsm + FH_KS_OFF;
    __half* Vs = hsm + FH_VS_OFF;
    __half* Ps = hsm + FH_PS_OFF;
    uint32_t vs_base = smem_u32(Vs);

    int tid = threadIdx.x, lane = tid & 31, wid = tid >> 5;
    int gid = lane >> 2, tig = lane & 3;
    int qb = gridDim.x - 1 - blockIdx.x;      // heavy tiles first
    int h = blockIdx.y, b = blockIdx.z;
    int kvh = h >> 2;
    int q0 = qb * 128;
    int rbase = wid * 16 + gid;

    // Load Q tile (128 x 128 halves) from packed buffer
    const __half* Qg = QKV + (size_t)(b * SS + q0) * QKVN + h * HD;
    #pragma unroll
    for (int it = 0; it < 8; it++) {
        int chunk = tid + it * 256;
        int r = chunk >> 4, c8 = (chunk & 15) * 8;
        *(uint4*)&Qs[r * HQS + c8] = *(const uint4*)(Qg + (size_t)r * QKVN + c8);
    }

    float of[16][4];
    #pragma unroll
    for (int nt = 0; nt < 16; nt++)
        #pragma unroll
        for (int r = 0; r < 4; r++) of[nt][r] = 0.f;
    float m_i[2] = {-1e30f, -1e30f}, l_i[2] = {0.f, 0.f};
    const float scale = 0.088388347648318447f;   // 1/sqrt(128)

    int ktiles = 2 * qb + 2;
    for (int kt = 0; kt < ktiles; kt++) {
        int k0 = kt * 64;
        const __half* Kg = QKV + (size_t)(b * SS + k0) * QKVN + HIDD + kvh * HD;
        const __half* Vg = Kg + KVD;

        __syncthreads();
        #pragma unroll
        for (int it = 0; it < 4; it++) {
            int chunk = tid + it * 256;
            int r = chunk >> 4, c8 = (chunk & 15) * 8;
            *(uint4*)&Ks[r * HQS + c8] = *(const uint4*)(Kg + (size_t)r * QKVN + c8);
            *(uint4*)&Vs[r * HQS + c8] = *(const uint4*)(Vg + (size_t)r * QKVN + c8);
        }
        __syncthreads();

        // ---- S = Q K^T : warp tile 16 x 64, 8 k16 steps ----
        float sf[8][4];
        #pragma unroll
        for (int nt = 0; nt < 8; nt++)
            #pragma unroll
            for (int r = 0; r < 4; r++) sf[nt][r] = 0.f;

        #pragma unroll
        for (int kb = 0; kb < 8; kb++) {
            uint32_t af[4];
            const char* qr = (const char*)Qs + rbase * (HQS * 2) + kb * 32 + tig * 4;
            af[0] = *(const uint32_t*)qr;
            af[1] = *(const uint32_t*)(qr + 8 * HQS * 2);
            af[2] = *(const uint32_t*)(qr + 16);
            af[3] = *(const uint32_t*)(qr + 8 * HQS * 2 + 16);
            #pragma unroll
            for (int nt = 0; nt < 8; nt++) {
                uint32_t bf[2];
                const char* kr = (const char*)Ks + (nt * 8 + gid) * (HQS * 2) + kb * 32 + tig * 4;
                bf[0] = *(const uint32_t*)kr;
                bf[1] = *(const uint32_t*)(kr + 16);
                mma_f16(sf[nt], af, bf);
            }
        }

        // ---- online softmax (rows warp-owned; tig-group shfls) ----
        bool need_mask = (kt >= 2 * qb);
        #pragma unroll
        for (int i = 0; i < 2; i++) {
            int grow = q0 + rbase + i * 8;
            float vmax = -1e30f;
            #pragma unroll
            for (int nt = 0; nt < 8; nt++) {
                float v0 = sf[nt][i * 2 + 0] * scale;
                float v1 = sf[nt][i * 2 + 1] * scale;
                if (need_mask) {
                    int c0 = k0 + nt * 8 + 2 * tig;
                    if (c0 > grow)     v0 = -1e30f;
                    if (c0 + 1 > grow) v1 = -1e30f;
                }
                sf[nt][i * 2 + 0] = v0;
                sf[nt][i * 2 + 1] = v1;
                vmax = fmaxf(vmax, fmaxf(v0, v1));
            }
            vmax = fmaxf(vmax, __shfl_xor_sync(0xffffffffu, vmax, 1));
            vmax = fmaxf(vmax, __shfl_xor_sync(0xffffffffu, vmax, 2));
            float mn = fmaxf(m_i[i], vmax);
            float al = __expf(m_i[i] - mn);
            m_i[i] = mn;
            float rs = 0.f;
            #pragma unroll
            for (int nt = 0; nt < 8; nt++) {
                float e0 = __expf(sf[nt][i * 2 + 0] - mn);
                float e1 = __expf(sf[nt][i * 2 + 1] - mn);
                rs += e0 + e1;
                *(__half2*)((char*)Ps + (rbase + i * 8) * (HPS * 2) + (nt * 8 + 2 * tig) * 2)
                    = __float22half2_rn(make_float2(e0, e1));
            }
            rs += __shfl_xor_sync(0xffffffffu, rs, 1);
            rs += __shfl_xor_sync(0xffffffffu, rs, 2);
            l_i[i] = l_i[i] * al + rs;
            #pragma unroll
            for (int nt = 0; nt < 16; nt++) {
                of[nt][i * 2 + 0] *= al;
                of[nt][i * 2 + 1] *= al;
            }
        }
        __syncwarp();

        // ---- O += P V : 2 passes of 2 k16 steps; V via ldmatrix.trans ----
        #pragma unroll
        for (int pass = 0; pass < 2; pass++) {
            uint32_t pa[2][4];
            const char* pr = (const char*)Ps + rbase * (HPS * 2) + pass * 64 + tig * 4;
            #pragma unroll
            for (int ks = 0; ks < 2; ks++) {
                pa[ks][0] = *(const uint32_t*)(pr + ks * 32);
                pa[ks][1] = *(const uint32_t*)(pr + ks * 32 + 8 * HPS * 2);
                pa[ks][2] = *(const uint32_t*)(pr + ks * 32 + 16);
                pa[ks][3] = *(const uint32_t*)(pr + ks * 32 + 8 * HPS * 2 + 16);
            }
            uint32_t vrow = vs_base + (pass * 32 + lane) * (HQS * 2);
            #pragma unroll
            for (int nt = 0; nt < 16; nt++) {
                uint32_t vb[4];
                ldsm_x4_trans(vb, vrow + nt * 16);
                mma_f16(of[nt], pa[0], vb);
                mma_f16(of[nt], pa[1], vb + 2);
            }
        }
    }

    // ---- epilogue: Y = O / l (fp16; feeds Wo gemm) ----
    __half* Yg = Y + (size_t)(b * SS + q0) * HIDD + h * HD;
    #pragma unroll
    for (int i = 0; i < 2; i++) {
        float inv = 1.0f / l_i[i];
        int r = rbase + i * 8;
        #pragma unroll
        for (int nt = 0; nt < 16; nt++) {
            *(__half2*)&Yg[(size_t)r * HIDD + nt * 8 + 2 * tig] =
                __float22half2_rn(make_float2(of[nt][i * 2 + 0] * inv,
                                              of[nt][i * 2 + 1] * inv));
        }
    }
}

// ============================================================================
// Launch
// ============================================================================
extern "C" void kernel_launch(void* const* d_in, const int* in_sizes, int n_in,
                              void* d_out, int out_size)
{
    const float* x  = (const float*)d_in[0];
    const float* cs = (const float*)d_in[1];
    const float* sn = (const float*)d_in[2];
    const float* Wq = (const float*)d_in[3];
    const float* Wk = (const float*)d_in[4];
    const float* Wv = (const float*)d_in[5];
    const float* Wo = (const float*)d_in[6];
    float* out = (float*)d_out;

    __half *xh, *wqkv, *woh, *qkv, *yh;
    cudaGetSymbolAddress((void**)&xh,   g_xh);
    cudaGetSymbolAddress((void**)&wqkv, g_wqkv);
    cudaGetSymbolAddress((void**)&woh,  g_woh);
    cudaGetSymbolAddress((void**)&qkv,  g_qkv);
    cudaGetSymbolAddress((void**)&yh,   g_yh);

    const int M = BB * SS;   // 4096

    cudaFuncSetAttribute(gemm_h,  cudaFuncAttributeMaxDynamicSharedMemorySize, GH_SMEM);
    cudaFuncSetAttribute(flash_h, cudaFuncAttributeMaxDynamicSharedMemorySize, FLASH_H_BYTES);

    // f32 -> f16 conversion; Wq|Wk|Wv concatenated into one weight buffer
    f2h_cvt<<<(M * HIDD / 8 + 255) / 256, 256>>>(x, xh, M * HIDD);
    f2h_cvt<<<(HIDD * HIDD / 8 + 255) / 256, 256>>>(Wq, wqkv, HIDD * HIDD);
    f2h_cvt<<<(KVD * HIDD / 8 + 255) / 256, 256>>>(Wk, wqkv + (size_t)HIDD * HIDD, KVD * HIDD);
    f2h_cvt<<<(KVD * HIDD / 8 + 255) / 256, 256>>>(Wv, wqkv + (size_t)(HIDD + KVD) * HIDD, KVD * HIDD);
    f2h_cvt<<<(HIDD * HIDD / 8 + 255) / 256, 256>>>(Wo, woh, HIDD * HIDD);

    // fused QKV projection with RoPE epilogue on q,k columns (< 2560)
    gemm_h<<<dim3(QKVN / 128, M / 128), 256, GH_SMEM>>>(
        xh, wqkv, qkv, M, QKVN, HIDD, 1, cs, sn, HIDD + KVD);

    flash_h<<<dim3(SS / 128, NH, BB), 256, FLASH_H_BYTES>>>(qkv, yh);

    gemm_h<<<dim3(HIDD / 128, M / 128), 256, GH_SMEM>>>(
        yh, woh, out, M, HIDD, HIDD, 0, (const float*)0, (const float*)0, 0);
}

// round 15
// speedup vs baseline: 6.0617x; 1.0974x over previous
#include <cuda_runtime.h>
#include <cuda_fp16.h>
#include <cstdint>

// Problem constants (fixed shapes from reference)
#define BB   2
#define SS   2048
#define HIDD 2048
#define NH   16
#define NKV  4
#define HD   128
#define KVD  (NKV * HD)   // 512
#define QKVN (HIDD + 2 * KVD)   // 3072 packed q|k|v columns

// Scratch (allocation-free rule: __device__ globals), fp16 pipeline
__device__ __half g_xh[BB * SS * HIDD];
__device__ __half g_wqkv[QKVN * HIDD];      // rows: Wq(2048) | Wk(512) | Wv(512)
__device__ __half g_woh[HIDD * HIDD];
__device__ __half g_qkv[BB * SS * QKVN];    // packed per-token q|k|v (rope applied)
__device__ __half g_yh[BB * SS * HIDD];     // attention output

// ---- helpers ----
__device__ __forceinline__ uint32_t smem_u32(const void* p) {
    uint32_t a;
    asm("{ .reg .u64 t; cvta.to.shared.u64 t, %1; cvt.u32.u64 %0, t; }"
        : "=r"(a) : "l"(p));
    return a;
}
__device__ __forceinline__ void cp_async16(uint32_t dst, const void* src) {
    asm volatile("cp.async.cg.shared.global [%0], [%1], 16;" :: "r"(dst), "l"(src));
}
#define CP_COMMIT() asm volatile("cp.async.commit_group;" ::: "memory")
#define CP_WAIT2()  asm volatile("cp.async.wait_group 2;" ::: "memory")

// mma.sync fp16 m16n8k16, fp32 accumulate (base sm_80+ PTX)
__device__ __forceinline__ void mma_f16(float* c, const uint32_t* a, const uint32_t* b) {
    asm volatile(
        "mma.sync.aligned.m16n8k16.row.col.f32.f16.f16.f32 "
        "{%0,%1,%2,%3}, {%4,%5,%6,%7}, {%8,%9}, {%0,%1,%2,%3};"
        : "+f"(c[0]), "+f"(c[1]), "+f"(c[2]), "+f"(c[3])
        : "r"(a[0]), "r"(a[1]), "r"(a[2]), "r"(a[3]), "r"(b[0]), "r"(b[1]));
}
// ldmatrix x4 (base sm_75+ PTX)
__device__ __forceinline__ void ldsm_x4(uint32_t* r, uint32_t addr) {
    asm volatile(
        "ldmatrix.sync.aligned.m8n8.x4.shared.b16 {%0,%1,%2,%3}, [%4];"
        : "=r"(r[0]), "=r"(r[1]), "=r"(r[2]), "=r"(r[3]) : "r"(addr));
}
__device__ __forceinline__ void ldsm_x4_trans(uint32_t* r, uint32_t addr) {
    asm volatile(
        "ldmatrix.sync.aligned.m8n8.x4.trans.shared.b16 {%0,%1,%2,%3}, [%4];"
        : "=r"(r[0]), "=r"(r[1]), "=r"(r[2]), "=r"(r[3]) : "r"(addr));
}

// ============================================================================
// Fused f32 -> f16 (RN) over the five GEMM operands in ONE launch.
// Segment lengths are compile-time constants of this problem.
// ============================================================================
#define CVT_L0 (BB * SS * HIDD)       // x       8388608
#define CVT_L1 (HIDD * HIDD)          // Wq      4194304
#define CVT_L2 (KVD * HIDD)           // Wk      1048576
#define CVT_L3 (KVD * HIDD)           // Wv      1048576
#define CVT_L4 (HIDD * HIDD)          // Wo      4194304
#define CVT_TOT (CVT_L0 + CVT_L1 + CVT_L2 + CVT_L3 + CVT_L4)   // 18874368

__global__ void f2h_cvt_all(
    const float* __restrict__ x,  const float* __restrict__ wq,
    const float* __restrict__ wk, const float* __restrict__ wv,
    const float* __restrict__ wo,
    __half* __restrict__ xh, __half* __restrict__ wqkv, __half* __restrict__ woh)
{
    long long i = (long long)(blockIdx.x * blockDim.x + threadIdx.x) * 8;
    if (i >= CVT_TOT) return;
    const float* src;
    __half* dst;
    long long off = i;
    if (off < CVT_L0)                    { src = x;  dst = xh; }
    else if ((off -= CVT_L0) < CVT_L1)   { src = wq; dst = wqkv; }
    else if ((off -= CVT_L1) < CVT_L2)   { src = wk; dst = wqkv + (size_t)CVT_L1; }
    else if ((off -= CVT_L2) < CVT_L3)   { src = wv; dst = wqkv + (size_t)(CVT_L1 + CVT_L2); }
    else { off -= CVT_L3;                  src = wo; dst = woh; }
    float4 a = *(const float4*)(src + off);
    float4 b = *(const float4*)(src + off + 4);
    __half2 h0 = __float22half2_rn(make_float2(a.x, a.y));
    __half2 h1 = __float22half2_rn(make_float2(a.z, a.w));
    __half2 h2 = __float22half2_rn(make_float2(b.x, b.y));
    __half2 h3 = __float22half2_rn(make_float2(b.z, b.w));
    *(uint4*)(dst + off) = make_uint4(*(uint32_t*)&h0, *(uint32_t*)&h1,
                                      *(uint32_t*)&h2, *(uint32_t*)&h3);
}

// ============================================================================
// FP16 mma GEMM:  C[M,N] = A[M,K] @ B[N,K]^T  (row-major; M,N%128, K%32)
// 128x128 CTA tile, 8 warps of 32x64, K-chunk 32 halves, 4-stage cp.async ring.
// Smem row stride 40 halves; fragments loaded via ldmatrix.x4 (conflict-free:
// 80B row stride -> 8 rows cover all eight 16B bank groups).
// ONE barrier per k-stage (load of stage s+3 overwrites buffer consumed at s-1,
// which barrier(s) already ordered).
// ============================================================================
#define GH_STAGE_BYTES 20480                 // (128+128) rows * 40 halves * 2B
#define GH_SMEM (4 * GH_STAGE_BYTES)         // 81920

__device__ __forceinline__ void gemm_load_h(
    uint32_t sbase, const __half* __restrict__ Ag, const __half* __restrict__ Bg,
    int K, int kt, int tid)
{
    int row = tid >> 1;
    int c = (tid & 1) * 16;
    const __half* sa = Ag + (size_t)row * K + kt * 32 + c;
    const __half* sb = Bg + (size_t)row * K + kt * 32 + c;
    uint32_t da = sbase + (row * 40 + c) * 2;
    uint32_t db = sbase + (128 * 40 + row * 40 + c) * 2;
    cp_async16(da, sa);       cp_async16(da + 16, sa + 8);
    cp_async16(db, sb);       cp_async16(db + 16, sb + 8);
}

__global__ __launch_bounds__(256, 2) void gemm_h(
    const __half* __restrict__ A, const __half* __restrict__ B,
    void* __restrict__ Cv, int M, int N, int K, int out_half,
    const float* __restrict__ cs, const float* __restrict__ sn, int rope_n)
{
    extern __shared__ __align__(16) char smc[];
    int tid = threadIdx.x;
    int lane = tid & 31, wid = tid >> 5;
    int gid = lane >> 2, tig = lane & 3;
    int wm = wid & 3, wn = wid >> 2;
    int m0 = blockIdx.y * 128, n0 = blockIdx.x * 128;

    const __half* Ag = A + (size_t)m0 * K;
    const __half* Bg = B + (size_t)n0 * K;
    uint32_t sb0 = smem_u32(smc);
    int nk = K / 32;

    // per-lane ldmatrix address component: row (lane&15), k-half (lane>>4)
    uint32_t lrow = (lane & 15) * 80 + (lane >> 4) * 16;

    float acc[2][8][4];
    #pragma unroll
    for (int i = 0; i < 2; i++)
        #pragma unroll
        for (int j = 0; j < 8; j++)
            #pragma unroll
            for (int r = 0; r < 4; r++) acc[i][j][r] = 0.f;

    #pragma unroll
    for (int s = 0; s < 3; s++) {
        gemm_load_h(sb0 + s * GH_STAGE_BYTES, Ag, Bg, K, s, tid);
        CP_COMMIT();
    }

    for (int s = 0; s < nk; s++) {
        CP_WAIT2();
        __syncthreads();
        if (s + 3 < nk)
            gemm_load_h(sb0 + ((s + 3) & 3) * GH_STAGE_BYTES, Ag, Bg, K, s + 3, tid);
        CP_COMMIT();

        uint32_t stage = sb0 + (s & 3) * GH_STAGE_BYTES;
        uint32_t a_base = stage + (wm * 32) * 80 + lrow;
        uint32_t b_base = stage + 128 * 80 + (wn * 64) * 80 + lrow;

        #pragma unroll
        for (int ks = 0; ks < 2; ks++) {
            int kb2 = ks * 32;
            uint32_t af[2][4], bf[8][2];
            #pragma unroll
            for (int mt = 0; mt < 2; mt++)
                ldsm_x4(af[mt], a_base + mt * (16 * 80) + kb2);
            #pragma unroll
            for (int ntp = 0; ntp < 4; ntp++) {
                uint32_t r[4];
                ldsm_x4(r, b_base + ntp * (16 * 80) + kb2);
                bf[2 * ntp][0] = r[0]; bf[2 * ntp + 1][0] = r[1];
                bf[2 * ntp][1] = r[2]; bf[2 * ntp + 1][1] = r[3];
            }
            #pragma unroll
            for (int mt = 0; mt < 2; mt++)
                #pragma unroll
                for (int nt = 0; nt < 8; nt++)
                    mma_f16(acc[mt][nt], af[mt], bf[nt]);
        }
    }

    if (out_half) {
        __half* C = (__half*)Cv;
        #pragma unroll
        for (int mt = 0; mt < 2; mt++) {
            int r0 = m0 + wm * 32 + mt * 16 + gid;
            int s0 = r0 & (SS - 1), s1 = (r0 + 8) & (SS - 1);
            #pragma unroll
            for (int nt = 0; nt < 8; nt++) {
                int cc = n0 + wn * 64 + nt * 8 + 2 * tig;
                float2 p0 = make_float2(acc[mt][nt][0], acc[mt][nt][1]);
                float2 p1 = make_float2(acc[mt][nt][2], acc[mt][nt][3]);
                if (cc < rope_n) {
                    int i = (cc & 127) >> 1;
                    float c0 = cs[s0 * 64 + i], v0 = sn[s0 * 64 + i];
                    float c1 = cs[s1 * 64 + i], v1 = sn[s1 * 64 + i];
                    p0 = make_float2(p0.x * c0 - p0.y * v0, p0.x * v0 + p0.y * c0);
                    p1 = make_float2(p1.x * c1 - p1.y * v1, p1.x * v1 + p1.y * c1);
                }
                *(__half2*)&C[(size_t)r0 * N + cc]       = __float22half2_rn(p0);
                *(__half2*)&C[(size_t)(r0 + 8) * N + cc] = __float22half2_rn(p1);
            }
        }
    } else {
        float* C = (float*)Cv;
        #pragma unroll
        for (int mt = 0; mt < 2; mt++) {
            int r = m0 + wm * 32 + mt * 16 + gid;
            #pragma unroll
            for (int nt = 0; nt < 8; nt++) {
                int cc = n0 + wn * 64 + nt * 8 + 2 * tig;
                *(float2*)&C[(size_t)r * N + cc]       = make_float2(acc[mt][nt][0], acc[mt][nt][1]);
                *(float2*)&C[(size_t)(r + 8) * N + cc] = make_float2(acc[mt][nt][2], acc[mt][nt][3]);
            }
        }
    }
}

// ============================================================================
// Causal flash attention on mma.sync fp16 (fp32 softmax + accumulators).
// (unchanged from R14 — reads packed qkv, BQ=128, BK=64, 8 warps)
// ============================================================================
#define HQS 136
#define HPS 72
#define FH_KS_OFF (128 * HQS)
#define FH_VS_OFF (FH_KS_OFF + 64 * HQS)
#define FH_PS_OFF (FH_VS_OFF + 64 * HQS)
#define FLASH_H_BYTES ((FH_PS_OFF + 128 * HPS) * 2)    // 88064

__global__ __launch_bounds__(256, 2) void flash_h(
    const __half* __restrict__ QKV, __half* __restrict__ Y)
{
    extern __shared__ __align__(16) __half hsm[];
    __half* Qs = hsm;
    __half* Ks = hsm + FH_KS_OFF;
    __half* Vs = hsm + FH_VS_OFF;
    __half* Ps = hsm + FH_PS_OFF;
    uint32_t vs_base = smem_u32(Vs);

    int tid = threadIdx.x, lane = tid & 31, wid = tid >> 5;
    int gid = lane >> 2, tig = lane & 3;
    int qb = gridDim.x - 1 - blockIdx.x;      // heavy tiles first
    int h = blockIdx.y, b = blockIdx.z;
    int kvh = h >> 2;
    int q0 = qb * 128;
    int rbase = wid * 16 + gid;

    const __half* Qg = QKV + (size_t)(b * SS + q0) * QKVN + h * HD;
    #pragma unroll
    for (int it = 0; it < 8; it++) {
        int chunk = tid + it * 256;
        int r = chunk >> 4, c8 = (chunk & 15) * 8;
        *(uint4*)&Qs[r * HQS + c8] = *(const uint4*)(Qg + (size_t)r * QKVN + c8);
    }

    float of[16][4];
    #pragma unroll
    for (int nt = 0; nt < 16; nt++)
        #pragma unroll
        for (int r = 0; r < 4; r++) of[nt][r] = 0.f;
    float m_i[2] = {-1e30f, -1e30f}, l_i[2] = {0.f, 0.f};
    const float scale = 0.088388347648318447f;   // 1/sqrt(128)

    int ktiles = 2 * qb + 2;
    for (int kt = 0; kt < ktiles; kt++) {
        int k0 = kt * 64;
        const __half* Kg = QKV + (size_t)(b * SS + k0) * QKVN + HIDD + kvh * HD;
        const __half* Vg = Kg + KVD;

        __syncthreads();
        #pragma unroll
        for (int it = 0; it < 4; it++) {
            int chunk = tid + it * 256;
            int r = chunk >> 4, c8 = (chunk & 15) * 8;
            *(uint4*)&Ks[r * HQS + c8] = *(const uint4*)(Kg + (size_t)r * QKVN + c8);
            *(uint4*)&Vs[r * HQS + c8] = *(const uint4*)(Vg + (size_t)r * QKVN + c8);
        }
        __syncthreads();

        float sf[8][4];
        #pragma unroll
        for (int nt = 0; nt < 8; nt++)
            #pragma unroll
            for (int r = 0; r < 4; r++) sf[nt][r] = 0.f;

        #pragma unroll
        for (int kb = 0; kb < 8; kb++) {
            uint32_t af[4];
            const char* qr = (const char*)Qs + rbase * (HQS * 2) + kb * 32 + tig * 4;
            af[0] = *(const uint32_t*)qr;
            af[1] = *(const uint32_t*)(qr + 8 * HQS * 2);
            af[2] = *(const uint32_t*)(qr + 16);
            af[3] = *(const uint32_t*)(qr + 8 * HQS * 2 + 16);
            #pragma unroll
            for (int nt = 0; nt < 8; nt++) {
                uint32_t bf[2];
                const char* kr = (const char*)Ks + (nt * 8 + gid) * (HQS * 2) + kb * 32 + tig * 4;
                bf[0] = *(const uint32_t*)kr;
                bf[1] = *(const uint32_t*)(kr + 16);
                mma_f16(sf[nt], af, bf);
            }
        }

        bool need_mask = (kt >= 2 * qb);
        #pragma unroll
        for (int i = 0; i < 2; i++) {
            int grow = q0 + rbase + i * 8;
            float vmax = -1e30f;
            #pragma unroll
            for (int nt = 0; nt < 8; nt++) {
                float v0 = sf[nt][i * 2 + 0] * scale;
                float v1 = sf[nt][i * 2 + 1] * scale;
                if (need_mask) {
                    int c0 = k0 + nt * 8 + 2 * tig;
                    if (c0 > grow)     v0 = -1e30f;
                    if (c0 + 1 > grow) v1 = -1e30f;
                }
                sf[nt][i * 2 + 0] = v0;
                sf[nt][i * 2 + 1] = v1;
                vmax = fmaxf(vmax, fmaxf(v0, v1));
            }
            vmax = fmaxf(vmax, __shfl_xor_sync(0xffffffffu, vmax, 1));
            vmax = fmaxf(vmax, __shfl_xor_sync(0xffffffffu, vmax, 2));
            float mn = fmaxf(m_i[i], vmax);
            float al = __expf(m_i[i] - mn);
            m_i[i] = mn;
            float rs = 0.f;
            #pragma unroll
            for (int nt = 0; nt < 8; nt++) {
                float e0 = __expf(sf[nt][i * 2 + 0] - mn);
                float e1 = __expf(sf[nt][i * 2 + 1] - mn);
                rs += e0 + e1;
                *(__half2*)((char*)Ps + (rbase + i * 8) * (HPS * 2) + (nt * 8 + 2 * tig) * 2)
                    = __float22half2_rn(make_float2(e0, e1));
            }
            rs += __shfl_xor_sync(0xffffffffu, rs, 1);
            rs += __shfl_xor_sync(0xffffffffu, rs, 2);
            l_i[i] = l_i[i] * al + rs;
            #pragma unroll
            for (int nt = 0; nt < 16; nt++) {
                of[nt][i * 2 + 0] *= al;
                of[nt][i * 2 + 1] *= al;
            }
        }
        __syncwarp();

        #pragma unroll
        for (int pass = 0; pass < 2; pass++) {
            uint32_t pa[2][4];
            const char* pr = (const char*)Ps + rbase * (HPS * 2) + pass * 64 + tig * 4;
            #pragma unroll
            for (int ks = 0; ks < 2; ks++) {
                pa[ks][0] = *(const uint32_t*)(pr + ks * 32);
                pa[ks][1] = *(const uint32_t*)(pr + ks * 32 + 8 * HPS * 2);
                pa[ks][2] = *(const uint32_t*)(pr + ks * 32 + 16);
                pa[ks][3] = *(const uint32_t*)(pr + ks * 32 + 8 * HPS * 2 + 16);
            }
            uint32_t vrow = vs_base + (pass * 32 + lane) * (HQS * 2);
            #pragma unroll
            for (int nt = 0; nt < 16; nt++) {
                uint32_t vb[4];
                ldsm_x4_trans(vb, vrow + nt * 16);
                mma_f16(of[nt], pa[0], vb);
                mma_f16(of[nt], pa[1], vb + 2);
            }
        }
    }

    __half* Yg = Y + (size_t)(b * SS + q0) * HIDD + h * HD;
    #pragma unroll
    for (int i = 0; i < 2; i++) {
        float inv = 1.0f / l_i[i];
        int r = rbase + i * 8;
        #pragma unroll
        for (int nt = 0; nt < 16; nt++) {
            *(__half2*)&Yg[(size_t)r * HIDD + nt * 8 + 2 * tig] =
                __float22half2_rn(make_float2(of[nt][i * 2 + 0] * inv,
                                              of[nt][i * 2 + 1] * inv));
        }
    }
}

// ============================================================================
// Launch
// ============================================================================
extern "C" void kernel_launch(void* const* d_in, const int* in_sizes, int n_in,
                              void* d_out, int out_size)
{
    const float* x  = (const float*)d_in[0];
    const float* cs = (const float*)d_in[1];
    const float* sn = (const float*)d_in[2];
    const float* Wq = (const float*)d_in[3];
    const float* Wk = (const float*)d_in[4];
    const float* Wv = (const float*)d_in[5];
    const float* Wo = (const float*)d_in[6];
    float* out = (float*)d_out;

    __half *xh, *wqkv, *woh, *qkv, *yh;
    cudaGetSymbolAddress((void**)&xh,   g_xh);
    cudaGetSymbolAddress((void**)&wqkv, g_wqkv);
    cudaGetSymbolAddress((void**)&woh,  g_woh);
    cudaGetSymbolAddress((void**)&qkv,  g_qkv);
    cudaGetSymbolAddress((void**)&yh,   g_yh);

    const int M = BB * SS;   // 4096

    cudaFuncSetAttribute(gemm_h,  cudaFuncAttributeMaxDynamicSharedMemorySize, GH_SMEM);
    cudaFuncSetAttribute(flash_h, cudaFuncAttributeMaxDynamicSharedMemorySize, FLASH_H_BYTES);

    // single fused f32 -> f16 conversion pass over all five operands
    f2h_cvt_all<<<(CVT_TOT / 8 + 255) / 256, 256>>>(x, Wq, Wk, Wv, Wo, xh, wqkv, woh);

    // fused QKV projection with RoPE epilogue on q,k columns (< 2560)
    gemm_h<<<dim3(QKVN / 128, M / 128), 256, GH_SMEM>>>(
        xh, wqkv, qkv, M, QKVN, HIDD, 1, cs, sn, HIDD + KVD);

    flash_h<<<dim3(SS / 128, NH, BB), 256, FLASH_H_BYTES>>>(qkv, yh);

    gemm_h<<<dim3(HIDD / 128, M / 128), 256, GH_SMEM>>>(
        yh, woh, out, M, HIDD, HIDD, 0, (const float*)0, (const float*)0, 0);
}

// round 16
// speedup vs baseline: 6.4096x; 1.0574x over previous
#include <cuda_runtime.h>
#include <cuda_fp16.h>
#include <cstdint>

// Problem constants (fixed shapes from reference)
#define BB   2
#define SS   2048
#define HIDD 2048
#define NH   16
#define NKV  4
#define HD   128
#define KVD  (NKV * HD)   // 512
#define QKVN (HIDD + 2 * KVD)   // 3072 packed q|k|v columns

// Scratch (allocation-free rule: __device__ globals), fp16 pipeline
__device__ __half g_xh[BB * SS * HIDD];
__device__ __half g_wqkv[QKVN * HIDD];      // rows: Wq(2048) | Wk(512) | Wv(512)
__device__ __half g_woh[HIDD * HIDD];
__device__ __half g_qkv[BB * SS * QKVN];    // packed per-token q|k|v (rope applied)
__device__ __half g_yh[BB * SS * HIDD];     // attention output

// ---- helpers ----
__device__ __forceinline__ uint32_t smem_u32(const void* p) {
    uint32_t a;
    asm("{ .reg .u64 t; cvta.to.shared.u64 t, %1; cvt.u32.u64 %0, t; }"
        : "=r"(a) : "l"(p));
    return a;
}
__device__ __forceinline__ void cp_async16(uint32_t dst, const void* src) {
    asm volatile("cp.async.cg.shared.global [%0], [%1], 16;" :: "r"(dst), "l"(src));
}
#define CP_COMMIT() asm volatile("cp.async.commit_group;" ::: "memory")
#define CP_WAIT1()  asm volatile("cp.async.wait_group 1;" ::: "memory")

// mma.sync fp16 m16n8k16, fp32 accumulate (base sm_80+ PTX)
__device__ __forceinline__ void mma_f16(float* c, const uint32_t* a, const uint32_t* b) {
    asm volatile(
        "mma.sync.aligned.m16n8k16.row.col.f32.f16.f16.f32 "
        "{%0,%1,%2,%3}, {%4,%5,%6,%7}, {%8,%9}, {%0,%1,%2,%3};"
        : "+f"(c[0]), "+f"(c[1]), "+f"(c[2]), "+f"(c[3])
        : "r"(a[0]), "r"(a[1]), "r"(a[2]), "r"(a[3]), "r"(b[0]), "r"(b[1]));
}
// ldmatrix x4 (base sm_75+ PTX)
__device__ __forceinline__ void ldsm_x4(uint32_t* r, uint32_t addr) {
    asm volatile(
        "ldmatrix.sync.aligned.m8n8.x4.shared.b16 {%0,%1,%2,%3}, [%4];"
        : "=r"(r[0]), "=r"(r[1]), "=r"(r[2]), "=r"(r[3]) : "r"(addr));
}
__device__ __forceinline__ void ldsm_x4_trans(uint32_t* r, uint32_t addr) {
    asm volatile(
        "ldmatrix.sync.aligned.m8n8.x4.trans.shared.b16 {%0,%1,%2,%3}, [%4];"
        : "=r"(r[0]), "=r"(r[1]), "=r"(r[2]), "=r"(r[3]) : "r"(addr));
}

// ============================================================================
// Fused f32 -> f16 (RN) over the five GEMM operands in ONE launch.
// ============================================================================
#define CVT_L0 (BB * SS * HIDD)       // x
#define CVT_L1 (HIDD * HIDD)          // Wq
#define CVT_L2 (KVD * HIDD)           // Wk
#define CVT_L3 (KVD * HIDD)           // Wv
#define CVT_L4 (HIDD * HIDD)          // Wo
#define CVT_TOT (CVT_L0 + CVT_L1 + CVT_L2 + CVT_L3 + CVT_L4)

__global__ void f2h_cvt_all(
    const float* __restrict__ x,  const float* __restrict__ wq,
    const float* __restrict__ wk, const float* __restrict__ wv,
    const float* __restrict__ wo,
    __half* __restrict__ xh, __half* __restrict__ wqkv, __half* __restrict__ woh)
{
    long long i = (long long)(blockIdx.x * blockDim.x + threadIdx.x) * 8;
    if (i >= CVT_TOT) return;
    const float* src;
    __half* dst;
    long long off = i;
    if (off < CVT_L0)                    { src = x;  dst = xh; }
    else if ((off -= CVT_L0) < CVT_L1)   { src = wq; dst = wqkv; }
    else if ((off -= CVT_L1) < CVT_L2)   { src = wk; dst = wqkv + (size_t)CVT_L1; }
    else if ((off -= CVT_L2) < CVT_L3)   { src = wv; dst = wqkv + (size_t)(CVT_L1 + CVT_L2); }
    else { off -= CVT_L3;                  src = wo; dst = woh; }
    float4 a = *(const float4*)(src + off);
    float4 b = *(const float4*)(src + off + 4);
    __half2 h0 = __float22half2_rn(make_float2(a.x, a.y));
    __half2 h1 = __float22half2_rn(make_float2(a.z, a.w));
    __half2 h2 = __float22half2_rn(make_float2(b.x, b.y));
    __half2 h3 = __float22half2_rn(make_float2(b.z, b.w));
    *(uint4*)(dst + off) = make_uint4(*(uint32_t*)&h0, *(uint32_t*)&h1,
                                      *(uint32_t*)&h2, *(uint32_t*)&h3);
}

// ============================================================================
// FP16 mma GEMM:  C[M,N] = A[M,K] @ B[N,K]^T  (row-major; M,N%128, K%64)
// 128x128 CTA tile, 8 warps of 32x64.
// K-chunk 64 halves per stage, 3-stage cp.async ring (110.6KB smem, 2 CTA/SM).
// Smem row stride 72 halves (36 words %32==4 -> STS + ldmatrix conflict-free).
// One barrier per 64-half stage; register double-buffered fragments; stage
// s+2's cp.async issued before compute of stage s.
// ============================================================================
#define GH_ROWB 144                            // 72 halves * 2B per smem row
#define GH_STAGE_BYTES (256 * GH_ROWB)         // 36864
#define GH_SMEM (3 * GH_STAGE_BYTES)           // 110592

__device__ __forceinline__ void gemm_load_h(
    uint32_t sbase, const __half* __restrict__ Ag, const __half* __restrict__ Bg,
    int K, int kt, int tid)
{
    // A tile: 128 rows x 64 halves = 1024 16B chunks; B likewise.
    #pragma unroll
    for (int it = 0; it < 4; it++) {
        int c = tid + it * 256;
        int row = c >> 3, off = (c & 7) * 8;
        cp_async16(sbase + row * GH_ROWB + off * 2,
                   Ag + (size_t)row * K + kt * 64 + off);
    }
    #pragma unroll
    for (int it = 0; it < 4; it++) {
        int c = tid + it * 256;
        int row = c >> 3, off = (c & 7) * 8;
        cp_async16(sbase + (128 + row) * GH_ROWB + off * 2,
                   Bg + (size_t)row * K + kt * 64 + off);
    }
}

__global__ __launch_bounds__(256, 2) void gemm_h(
    const __half* __restrict__ A, const __half* __restrict__ B,
    void* __restrict__ Cv, int M, int N, int K, int out_half,
    const float* __restrict__ cs, const float* __restrict__ sn, int rope_n)
{
    extern __shared__ __align__(16) char smc[];
    int tid = threadIdx.x;
    int lane = tid & 31, wid = tid >> 5;
    int gid = lane >> 2, tig = lane & 3;
    int wm = wid & 3, wn = wid >> 2;
    int m0 = blockIdx.y * 128, n0 = blockIdx.x * 128;

    const __half* Ag = A + (size_t)m0 * K;
    const __half* Bg = B + (size_t)n0 * K;
    uint32_t sb0 = smem_u32(smc);
    int nk = K / 64;

    // per-lane ldmatrix address component: row (lane&15), k-half (lane>>4)
    uint32_t lrow = (lane & 15) * GH_ROWB + (lane >> 4) * 16;

    float acc[2][8][4];
    #pragma unroll
    for (int i = 0; i < 2; i++)
        #pragma unroll
        for (int j = 0; j < 8; j++)
            #pragma unroll
            for (int r = 0; r < 4; r++) acc[i][j][r] = 0.f;

    gemm_load_h(sb0, Ag, Bg, K, 0, tid);                    CP_COMMIT();
    gemm_load_h(sb0 + GH_STAGE_BYTES, Ag, Bg, K, 1, tid);   CP_COMMIT();

    uint32_t af[2][2][4], bf[2][8][2];

    for (int s = 0; s < nk; s++) {
        CP_WAIT1();
        __syncthreads();
        // fetch stage s+2 (overwrites buffer consumed at s-1; barrier ordered it)
        if (s + 2 < nk) {
            int buf = s + 2; buf -= (buf >= 3) ? 3 : 0; buf -= (buf >= 3) ? 3 : 0;
            // (s+2)%3 without div: s%3 cycles 0,1,2 — compute directly:
        }
        int b2 = (s + 2) % 3;
        if (s + 2 < nk)
            gemm_load_h(sb0 + b2 * GH_STAGE_BYTES, Ag, Bg, K, s + 2, tid);
        CP_COMMIT();

        uint32_t stage = sb0 + (s % 3) * GH_STAGE_BYTES;
        uint32_t a_base = stage + (wm * 32) * GH_ROWB + lrow;
        uint32_t b_base = stage + 128 * GH_ROWB + (wn * 64) * GH_ROWB + lrow;

        // ---- 4 k16 steps, register double-buffered fragments ----
        {
            #pragma unroll
            for (int mt = 0; mt < 2; mt++)
                ldsm_x4(af[0][mt], a_base + mt * (16 * GH_ROWB));
            #pragma unroll
            for (int ntp = 0; ntp < 4; ntp++) {
                uint32_t r[4];
                ldsm_x4(r, b_base + ntp * (16 * GH_ROWB));
                bf[0][2 * ntp][0] = r[0]; bf[0][2 * ntp + 1][0] = r[1];
                bf[0][2 * ntp][1] = r[2]; bf[0][2 * ntp + 1][1] = r[3];
            }
        }
        #pragma unroll
        for (int k = 0; k < 4; k++) {
            int cur = k & 1, nxt = cur ^ 1;
            if (k < 3) {
                int kb2 = (k + 1) * 32;
                #pragma unroll
                for (int mt = 0; mt < 2; mt++)
                    ldsm_x4(af[nxt][mt], a_base + mt * (16 * GH_ROWB) + kb2);
                #pragma unroll
                for (int ntp = 0; ntp < 4; ntp++) {
                    uint32_t r[4];
                    ldsm_x4(r, b_base + ntp * (16 * GH_ROWB) + kb2);
                    bf[nxt][2 * ntp][0] = r[0]; bf[nxt][2 * ntp + 1][0] = r[1];
                    bf[nxt][2 * ntp][1] = r[2]; bf[nxt][2 * ntp + 1][1] = r[3];
                }
            }
            #pragma unroll
            for (int mt = 0; mt < 2; mt++)
                #pragma unroll
                for (int nt = 0; nt < 8; nt++)
                    mma_f16(acc[mt][nt], af[cur][mt], bf[cur][nt]);
        }
    }

    if (out_half) {
        __half* C = (__half*)Cv;
        #pragma unroll
        for (int mt = 0; mt < 2; mt++) {
            int r0 = m0 + wm * 32 + mt * 16 + gid;
            int s0 = r0 & (SS - 1), s1 = (r0 + 8) & (SS - 1);
            #pragma unroll
            for (int nt = 0; nt < 8; nt++) {
                int cc = n0 + wn * 64 + nt * 8 + 2 * tig;
                float2 p0 = make_float2(acc[mt][nt][0], acc[mt][nt][1]);
                float2 p1 = make_float2(acc[mt][nt][2], acc[mt][nt][3]);
                if (cc < rope_n) {
                    int i = (cc & 127) >> 1;
                    float c0 = cs[s0 * 64 + i], v0 = sn[s0 * 64 + i];
                    float c1 = cs[s1 * 64 + i], v1 = sn[s1 * 64 + i];
                    p0 = make_float2(p0.x * c0 - p0.y * v0, p0.x * v0 + p0.y * c0);
                    p1 = make_float2(p1.x * c1 - p1.y * v1, p1.x * v1 + p1.y * c1);
                }
                *(__half2*)&C[(size_t)r0 * N + cc]       = __float22half2_rn(p0);
                *(__half2*)&C[(size_t)(r0 + 8) * N + cc] = __float22half2_rn(p1);
            }
        }
    } else {
        float* C = (float*)Cv;
        #pragma unroll
        for (int mt = 0; mt < 2; mt++) {
            int r = m0 + wm * 32 + mt * 16 + gid;
            #pragma unroll
            for (int nt = 0; nt < 8; nt++) {
                int cc = n0 + wn * 64 + nt * 8 + 2 * tig;
                *(float2*)&C[(size_t)r * N + cc]       = make_float2(acc[mt][nt][0], acc[mt][nt][1]);
                *(float2*)&C[(size_t)(r + 8) * N + cc] = make_float2(acc[mt][nt][2], acc[mt][nt][3]);
            }
        }
    }
}

// ============================================================================
// Causal flash attention on mma.sync fp16 (fp32 softmax + accumulators).
// (unchanged from R15 — reads packed qkv, BQ=128, BK=64, 8 warps)
// ============================================================================
#define HQS 136
#define HPS 72
#define FH_KS_OFF (128 * HQS)
#define FH_VS_OFF (FH_KS_OFF + 64 * HQS)
#define FH_PS_OFF (FH_VS_OFF + 64 * HQS)
#define FLASH_H_BYTES ((FH_PS_OFF + 128 * HPS) * 2)    // 88064

__global__ __launch_bounds__(256, 2) void flash_h(
    const __half* __restrict__ QKV, __half* __restrict__ Y)
{
    extern __shared__ __align__(16) __half hsm[];
    __half* Qs = hsm;
    __half* Ks = hsm + FH_KS_OFF;
    __half* Vs = hsm + FH_VS_OFF;
    __half* Ps = hsm + FH_PS_OFF;
    uint32_t vs_base = smem_u32(Vs);

    int tid = threadIdx.x, lane = tid & 31, wid = tid >> 5;
    int gid = lane >> 2, tig = lane & 3;
    int qb = gridDim.x - 1 - blockIdx.x;      // heavy tiles first
    int h = blockIdx.y, b = blockIdx.z;
    int kvh = h >> 2;
    int q0 = qb * 128;
    int rbase = wid * 16 + gid;

    const __half* Qg = QKV + (size_t)(b * SS + q0) * QKVN + h * HD;
    #pragma unroll
    for (int it = 0; it < 8; it++) {
        int chunk = tid + it * 256;
        int r = chunk >> 4, c8 = (chunk & 15) * 8;
        *(uint4*)&Qs[r * HQS + c8] = *(const uint4*)(Qg + (size_t)r * QKVN + c8);
    }

    float of[16][4];
    #pragma unroll
    for (int nt = 0; nt < 16; nt++)
        #pragma unroll
        for (int r = 0; r < 4; r++) of[nt][r] = 0.f;
    float m_i[2] = {-1e30f, -1e30f}, l_i[2] = {0.f, 0.f};
    const float scale = 0.088388347648318447f;   // 1/sqrt(128)

    int ktiles = 2 * qb + 2;
    for (int kt = 0; kt < ktiles; kt++) {
        int k0 = kt * 64;
        const __half* Kg = QKV + (size_t)(b * SS + k0) * QKVN + HIDD + kvh * HD;
        const __half* Vg = Kg + KVD;

        __syncthreads();
        #pragma unroll
        for (int it = 0; it < 4; it++) {
            int chunk = tid + it * 256;
            int r = chunk >> 4, c8 = (chunk & 15) * 8;
            *(uint4*)&Ks[r * HQS + c8] = *(const uint4*)(Kg + (size_t)r * QKVN + c8);
            *(uint4*)&Vs[r * HQS + c8] = *(const uint4*)(Vg + (size_t)r * QKVN + c8);
        }
        __syncthreads();

        float sf[8][4];
        #pragma unroll
        for (int nt = 0; nt < 8; nt++)
            #pragma unroll
            for (int r = 0; r < 4; r++) sf[nt][r] = 0.f;

        #pragma unroll
        for (int kb = 0; kb < 8; kb++) {
            uint32_t af[4];
            const char* qr = (const char*)Qs + rbase * (HQS * 2) + kb * 32 + tig * 4;
            af[0] = *(const uint32_t*)qr;
            af[1] = *(const uint32_t*)(qr + 8 * HQS * 2);
            af[2] = *(const uint32_t*)(qr + 16);
            af[3] = *(const uint32_t*)(qr + 8 * HQS * 2 + 16);
            #pragma unroll
            for (int nt = 0; nt < 8; nt++) {
                uint32_t bf[2];
                const char* kr = (const char*)Ks + (nt * 8 + gid) * (HQS * 2) + kb * 32 + tig * 4;
                bf[0] = *(const uint32_t*)kr;
                bf[1] = *(const uint32_t*)(kr + 16);
                mma_f16(sf[nt], af, bf);
            }
        }

        bool need_mask = (kt >= 2 * qb);
        #pragma unroll
        for (int i = 0; i < 2; i++) {
            int grow = q0 + rbase + i * 8;
            float vmax = -1e30f;
            #pragma unroll
            for (int nt = 0; nt < 8; nt++) {
                float v0 = sf[nt][i * 2 + 0] * scale;
                float v1 = sf[nt][i * 2 + 1] * scale;
                if (need_mask) {
                    int c0 = k0 + nt * 8 + 2 * tig;
                    if (c0 > grow)     v0 = -1e30f;
                    if (c0 + 1 > grow) v1 = -1e30f;
                }
                sf[nt][i * 2 + 0] = v0;
                sf[nt][i * 2 + 1] = v1;
                vmax = fmaxf(vmax, fmaxf(v0, v1));
            }
            vmax = fmaxf(vmax, __shfl_xor_sync(0xffffffffu, vmax, 1));
            vmax = fmaxf(vmax, __shfl_xor_sync(0xffffffffu, vmax, 2));
            float mn = fmaxf(m_i[i], vmax);
            float al = __expf(m_i[i] - mn);
            m_i[i] = mn;
            float rs = 0.f;
            #pragma unroll
            for (int nt = 0; nt < 8; nt++) {
                float e0 = __expf(sf[nt][i * 2 + 0] - mn);
                float e1 = __expf(sf[nt][i * 2 + 1] - mn);
                rs += e0 + e1;
                *(__half2*)((char*)Ps + (rbase + i * 8) * (HPS * 2) + (nt * 8 + 2 * tig) * 2)
                    = __float22half2_rn(make_float2(e0, e1));
            }
            rs += __shfl_xor_sync(0xffffffffu, rs, 1);
            rs += __shfl_xor_sync(0xffffffffu, rs, 2);
            l_i[i] = l_i[i] * al + rs;
            #pragma unroll
            for (int nt = 0; nt < 16; nt++) {
                of[nt][i * 2 + 0] *= al;
                of[nt][i * 2 + 1] *= al;
            }
        }
        __syncwarp();

        #pragma unroll
        for (int pass = 0; pass < 2; pass++) {
            uint32_t pa[2][4];
            const char* pr = (const char*)Ps + rbase * (HPS * 2) + pass * 64 + tig * 4;
            #pragma unroll
            for (int ks = 0; ks < 2; ks++) {
                pa[ks][0] = *(const uint32_t*)(pr + ks * 32);
                pa[ks][1] = *(const uint32_t*)(pr + ks * 32 + 8 * HPS * 2);
                pa[ks][2] = *(const uint32_t*)(pr + ks * 32 + 16);
                pa[ks][3] = *(const uint32_t*)(pr + ks * 32 + 8 * HPS * 2 + 16);
            }
            uint32_t vrow = vs_base + (pass * 32 + lane) * (HQS * 2);
            #pragma unroll
            for (int nt = 0; nt < 16; nt++) {
                uint32_t vb[4];
                ldsm_x4_trans(vb, vrow + nt * 16);
                mma_f16(of[nt], pa[0], vb);
                mma_f16(of[nt], pa[1], vb + 2);
            }
        }
    }

    __half* Yg = Y + (size_t)(b * SS + q0) * HIDD + h * HD;
    #pragma unroll
    for (int i = 0; i < 2; i++) {
        float inv = 1.0f / l_i[i];
        int r = rbase + i * 8;
        #pragma unroll
        for (int nt = 0; nt < 16; nt++) {
            *(__half2*)&Yg[(size_t)r * HIDD + nt * 8 + 2 * tig] =
                __float22half2_rn(make_float2(of[nt][i * 2 + 0] * inv,
                                              of[nt][i * 2 + 1] * inv));
        }
    }
}

// ============================================================================
// Launch
// ============================================================================
extern "C" void kernel_launch(void* const* d_in, const int* in_sizes, int n_in,
                              void* d_out, int out_size)
{
    const float* x  = (const float*)d_in[0];
    const float* cs = (const float*)d_in[1];
    const float* sn = (const float*)d_in[2];
    const float* Wq = (const float*)d_in[3];
    const float* Wk = (const float*)d_in[4];
    const float* Wv = (const float*)d_in[5];
    const float* Wo = (const float*)d_in[6];
    float* out = (float*)d_out;

    __half *xh, *wqkv, *woh, *qkv, *yh;
    cudaGetSymbolAddress((void**)&xh,   g_xh);
    cudaGetSymbolAddress((void**)&wqkv, g_wqkv);
    cudaGetSymbolAddress((void**)&woh,  g_woh);
    cudaGetSymbolAddress((void**)&qkv,  g_qkv);
    cudaGetSymbolAddress((void**)&yh,   g_yh);

    const int M = BB * SS;   // 4096

    cudaFuncSetAttribute(gemm_h,  cudaFuncAttributeMaxDynamicSharedMemorySize, GH_SMEM);
    cudaFuncSetAttribute(flash_h, cudaFuncAttributeMaxDynamicSharedMemorySize, FLASH_H_BYTES);

    // single fused f32 -> f16 conversion pass over all five operands
    f2h_cvt_all<<<(CVT_TOT / 8 + 255) / 256, 256>>>(x, Wq, Wk, Wv, Wo, xh, wqkv, woh);

    // fused QKV projection with RoPE epilogue on q,k columns (< 2560)
    gemm_h<<<dim3(QKVN / 128, M / 128), 256, GH_SMEM>>>(
        xh, wqkv, qkv, M, QKVN, HIDD, 1, cs, sn, HIDD + KVD);

    flash_h<<<dim3(SS / 128, NH, BB), 256, FLASH_H_BYTES>>>(qkv, yh);

    gemm_h<<<dim3(HIDD / 128, M / 128), 256, GH_SMEM>>>(
        yh, woh, out, M, HIDD, HIDD, 0, (const float*)0, (const float*)0, 0);
}

// round 17
// speedup vs baseline: 6.6420x; 1.0363x over previous
#include <cuda_runtime.h>
#include <cuda_fp16.h>
#include <cstdint>

// Problem constants (fixed shapes from reference)
#define BB   2
#define SS   2048
#define HIDD 2048
#define NH   16
#define NKV  4
#define HD   128
#define KVD  (NKV * HD)   // 512
#define QKVN (HIDD + 2 * KVD)   // 3072 packed q|k|v columns

// Scratch (allocation-free rule: __device__ globals), fp16 pipeline
__device__ __half g_xh[BB * SS * HIDD];
__device__ __half g_wqkv[QKVN * HIDD];      // rows: Wq(2048) | Wk(512) | Wv(512)
__device__ __half g_woh[HIDD * HIDD];
__device__ __half g_qkv[BB * SS * QKVN];    // packed per-token q|k|v (rope applied)
__device__ __half g_yh[BB * SS * HIDD];     // attention output

// ---- helpers ----
__device__ __forceinline__ uint32_t smem_u32(const void* p) {
    uint32_t a;
    asm("{ .reg .u64 t; cvta.to.shared.u64 t, %1; cvt.u32.u64 %0, t; }"
        : "=r"(a) : "l"(p));
    return a;
}
__device__ __forceinline__ void cp_async16(uint32_t dst, const void* src) {
    asm volatile("cp.async.cg.shared.global [%0], [%1], 16;" :: "r"(dst), "l"(src));
}
#define CP_COMMIT() asm volatile("cp.async.commit_group;" ::: "memory")
#define CP_WAIT1()  asm volatile("cp.async.wait_group 1;" ::: "memory")

// mma.sync fp16 m16n8k16, fp32 accumulate (base sm_80+ PTX)
__device__ __forceinline__ void mma_f16(float* c, const uint32_t* a, const uint32_t* b) {
    asm volatile(
        "mma.sync.aligned.m16n8k16.row.col.f32.f16.f16.f32 "
        "{%0,%1,%2,%3}, {%4,%5,%6,%7}, {%8,%9}, {%0,%1,%2,%3};"
        : "+f"(c[0]), "+f"(c[1]), "+f"(c[2]), "+f"(c[3])
        : "r"(a[0]), "r"(a[1]), "r"(a[2]), "r"(a[3]), "r"(b[0]), "r"(b[1]));
}
// ldmatrix x4 (base sm_75+ PTX)
__device__ __forceinline__ void ldsm_x4(uint32_t* r, uint32_t addr) {
    asm volatile(
        "ldmatrix.sync.aligned.m8n8.x4.shared.b16 {%0,%1,%2,%3}, [%4];"
        : "=r"(r[0]), "=r"(r[1]), "=r"(r[2]), "=r"(r[3]) : "r"(addr));
}
__device__ __forceinline__ void ldsm_x4_trans(uint32_t* r, uint32_t addr) {
    asm volatile(
        "ldmatrix.sync.aligned.m8n8.x4.trans.shared.b16 {%0,%1,%2,%3}, [%4];"
        : "=r"(r[0]), "=r"(r[1]), "=r"(r[2]), "=r"(r[3]) : "r"(addr));
}

// ============================================================================
// Fused f32 -> f16 (RN) over the five GEMM operands in ONE launch.
// ============================================================================
#define CVT_L0 (BB * SS * HIDD)       // x
#define CVT_L1 (HIDD * HIDD)          // Wq
#define CVT_L2 (KVD * HIDD)           // Wk
#define CVT_L3 (KVD * HIDD)           // Wv
#define CVT_L4 (HIDD * HIDD)          // Wo
#define CVT_TOT (CVT_L0 + CVT_L1 + CVT_L2 + CVT_L3 + CVT_L4)

__global__ void f2h_cvt_all(
    const float* __restrict__ x,  const float* __restrict__ wq,
    const float* __restrict__ wk, const float* __restrict__ wv,
    const float* __restrict__ wo,
    __half* __restrict__ xh, __half* __restrict__ wqkv, __half* __restrict__ woh)
{
    long long i = (long long)(blockIdx.x * blockDim.x + threadIdx.x) * 8;
    if (i >= CVT_TOT) return;
    const float* src;
    __half* dst;
    long long off = i;
    if (off < CVT_L0)                    { src = x;  dst = xh; }
    else if ((off -= CVT_L0) < CVT_L1)   { src = wq; dst = wqkv; }
    else if ((off -= CVT_L1) < CVT_L2)   { src = wk; dst = wqkv + (size_t)CVT_L1; }
    else if ((off -= CVT_L2) < CVT_L3)   { src = wv; dst = wqkv + (size_t)(CVT_L1 + CVT_L2); }
    else { off -= CVT_L3;                  src = wo; dst = woh; }
    float4 a = *(const float4*)(src + off);
    float4 b = *(const float4*)(src + off + 4);
    __half2 h0 = __float22half2_rn(make_float2(a.x, a.y));
    __half2 h1 = __float22half2_rn(make_float2(a.z, a.w));
    __half2 h2 = __float22half2_rn(make_float2(b.x, b.y));
    __half2 h3 = __float22half2_rn(make_float2(b.z, b.w));
    *(uint4*)(dst + off) = make_uint4(*(uint32_t*)&h0, *(uint32_t*)&h1,
                                      *(uint32_t*)&h2, *(uint32_t*)&h3);
}

// ============================================================================
// FP16 mma GEMM:  C[M,N] = A[M,K] @ B[N,K]^T  (row-major; M,N%128, K%64)
// 128x128 CTA tile, 8 warps of 32x64, K-chunk 64, 3-stage cp.async ring.
// Row stride 72 halves; ldmatrix fragments; register double-buffering;
// rotating buffer counters (no integer modulo in the mainloop).
// ============================================================================
#define GH_ROWB 144                            // 72 halves * 2B per smem row
#define GH_STAGE_BYTES (256 * GH_ROWB)         // 36864
#define GH_SMEM (3 * GH_STAGE_BYTES)           // 110592

__device__ __forceinline__ void gemm_load_h(
    uint32_t sbase, const __half* __restrict__ Ag, const __half* __restrict__ Bg,
    int K, int kt, int tid)
{
    #pragma unroll
    for (int it = 0; it < 4; it++) {
        int c = tid + it * 256;
        int row = c >> 3, off = (c & 7) * 8;
        cp_async16(sbase + row * GH_ROWB + off * 2,
                   Ag + (size_t)row * K + kt * 64 + off);
    }
    #pragma unroll
    for (int it = 0; it < 4; it++) {
        int c = tid + it * 256;
        int row = c >> 3, off = (c & 7) * 8;
        cp_async16(sbase + (128 + row) * GH_ROWB + off * 2,
                   Bg + (size_t)row * K + kt * 64 + off);
    }
}

__global__ __launch_bounds__(256, 2) void gemm_h(
    const __half* __restrict__ A, const __half* __restrict__ B,
    void* __restrict__ Cv, int M, int N, int K, int out_half,
    const float* __restrict__ cs, const float* __restrict__ sn, int rope_n)
{
    extern __shared__ __align__(16) char smc[];
    int tid = threadIdx.x;
    int lane = tid & 31, wid = tid >> 5;
    int gid = lane >> 2, tig = lane & 3;
    int wm = wid & 3, wn = wid >> 2;
    int m0 = blockIdx.y * 128, n0 = blockIdx.x * 128;

    const __half* Ag = A + (size_t)m0 * K;
    const __half* Bg = B + (size_t)n0 * K;
    uint32_t sb0 = smem_u32(smc);
    int nk = K / 64;

    // per-lane ldmatrix bases within a stage (hoisted; add stage offset only)
    uint32_t lrow   = (lane & 15) * GH_ROWB + (lane >> 4) * 16;
    uint32_t a_off  = (wm * 32) * GH_ROWB + lrow;
    uint32_t b_off  = 128 * GH_ROWB + (wn * 64) * GH_ROWB + lrow;

    float acc[2][8][4];
    #pragma unroll
    for (int i = 0; i < 2; i++)
        #pragma unroll
        for (int j = 0; j < 8; j++)
            #pragma unroll
            for (int r = 0; r < 4; r++) acc[i][j][r] = 0.f;

    gemm_load_h(sb0, Ag, Bg, K, 0, tid);                    CP_COMMIT();
    gemm_load_h(sb0 + GH_STAGE_BYTES, Ag, Bg, K, 1, tid);   CP_COMMIT();

    uint32_t af[2][2][4], bf[2][8][2];
    int bc = 0, bn = 2;                       // current / prefetch buffer ids

    for (int s = 0; s < nk; s++) {
        CP_WAIT1();
        __syncthreads();
        if (s + 2 < nk)
            gemm_load_h(sb0 + bn * GH_STAGE_BYTES, Ag, Bg, K, s + 2, tid);
        CP_COMMIT();

        uint32_t a_base = sb0 + bc * GH_STAGE_BYTES + a_off;
        uint32_t b_base = sb0 + bc * GH_STAGE_BYTES + b_off;

        {
            #pragma unroll
            for (int mt = 0; mt < 2; mt++)
                ldsm_x4(af[0][mt], a_base + mt * (16 * GH_ROWB));
            #pragma unroll
            for (int ntp = 0; ntp < 4; ntp++) {
                uint32_t r[4];
                ldsm_x4(r, b_base + ntp * (16 * GH_ROWB));
                bf[0][2 * ntp][0] = r[0]; bf[0][2 * ntp + 1][0] = r[1];
                bf[0][2 * ntp][1] = r[2]; bf[0][2 * ntp + 1][1] = r[3];
            }
        }
        #pragma unroll
        for (int k = 0; k < 4; k++) {
            int cur = k & 1, nxt = cur ^ 1;
            if (k < 3) {
                int kb2 = (k + 1) * 32;
                #pragma unroll
                for (int mt = 0; mt < 2; mt++)
                    ldsm_x4(af[nxt][mt], a_base + mt * (16 * GH_ROWB) + kb2);
                #pragma unroll
                for (int ntp = 0; ntp < 4; ntp++) {
                    uint32_t r[4];
                    ldsm_x4(r, b_base + ntp * (16 * GH_ROWB) + kb2);
                    bf[nxt][2 * ntp][0] = r[0]; bf[nxt][2 * ntp + 1][0] = r[1];
                    bf[nxt][2 * ntp][1] = r[2]; bf[nxt][2 * ntp + 1][1] = r[3];
                }
            }
            #pragma unroll
            for (int mt = 0; mt < 2; mt++)
                #pragma unroll
                for (int nt = 0; nt < 8; nt++)
                    mma_f16(acc[mt][nt], af[cur][mt], bf[cur][nt]);
        }
        bc = (bc == 2) ? 0 : bc + 1;
        bn = (bn == 2) ? 0 : bn + 1;
    }

    if (out_half) {
        __half* C = (__half*)Cv;
        #pragma unroll
        for (int mt = 0; mt < 2; mt++) {
            int r0 = m0 + wm * 32 + mt * 16 + gid;
            int s0 = r0 & (SS - 1), s1 = (r0 + 8) & (SS - 1);
            #pragma unroll
            for (int nt = 0; nt < 8; nt++) {
                int cc = n0 + wn * 64 + nt * 8 + 2 * tig;
                float2 p0 = make_float2(acc[mt][nt][0], acc[mt][nt][1]);
                float2 p1 = make_float2(acc[mt][nt][2], acc[mt][nt][3]);
                if (cc < rope_n) {
                    int i = (cc & 127) >> 1;
                    float c0 = cs[s0 * 64 + i], v0 = sn[s0 * 64 + i];
                    float c1 = cs[s1 * 64 + i], v1 = sn[s1 * 64 + i];
                    p0 = make_float2(p0.x * c0 - p0.y * v0, p0.x * v0 + p0.y * c0);
                    p1 = make_float2(p1.x * c1 - p1.y * v1, p1.x * v1 + p1.y * c1);
                }
                *(__half2*)&C[(size_t)r0 * N + cc]       = __float22half2_rn(p0);
                *(__half2*)&C[(size_t)(r0 + 8) * N + cc] = __float22half2_rn(p1);
            }
        }
    } else {
        float* C = (float*)Cv;
        #pragma unroll
        for (int mt = 0; mt < 2; mt++) {
            int r = m0 + wm * 32 + mt * 16 + gid;
            #pragma unroll
            for (int nt = 0; nt < 8; nt++) {
                int cc = n0 + wn * 64 + nt * 8 + 2 * tig;
                *(float2*)&C[(size_t)r * N + cc]       = make_float2(acc[mt][nt][0], acc[mt][nt][1]);
                *(float2*)&C[(size_t)(r + 8) * N + cc] = make_float2(acc[mt][nt][2], acc[mt][nt][3]);
            }
        }
    }
}

// ============================================================================
// Causal flash attention on mma.sync fp16 (fp32 softmax + accumulators).
// QK fragments now via ldmatrix.x4 (row stride 272B = 17*16B -> conflict-free).
// ============================================================================
#define HQS 136
#define HPS 72
#define FH_KS_OFF (128 * HQS)
#define FH_VS_OFF (FH_KS_OFF + 64 * HQS)
#define FH_PS_OFF (FH_VS_OFF + 64 * HQS)
#define FLASH_H_BYTES ((FH_PS_OFF + 128 * HPS) * 2)    // 88064

__global__ __launch_bounds__(256, 2) void flash_h(
    const __half* __restrict__ QKV, __half* __restrict__ Y)
{
    extern __shared__ __align__(16) __half hsm[];
    __half* Qs = hsm;
    __half* Ks = hsm + FH_KS_OFF;
    __half* Vs = hsm + FH_VS_OFF;
    __half* Ps = hsm + FH_PS_OFF;
    uint32_t vs_base = smem_u32(Vs);

    int tid = threadIdx.x, lane = tid & 31, wid = tid >> 5;
    int gid = lane >> 2, tig = lane & 3;
    int qb = gridDim.x - 1 - blockIdx.x;      // heavy tiles first
    int h = blockIdx.y, b = blockIdx.z;
    int kvh = h >> 2;
    int q0 = qb * 128;
    int rbase = wid * 16 + gid;

    // ldmatrix per-lane bases (row = lane&15, k-half = lane>>4)
    uint32_t lmrow   = (lane & 15) * (HQS * 2) + (lane >> 4) * 16;
    uint32_t qs_lm   = smem_u32(Qs) + (wid * 16) * (HQS * 2) + lmrow;
    uint32_t ks_lm   = smem_u32(Ks) + lmrow;

    const __half* Qg = QKV + (size_t)(b * SS + q0) * QKVN + h * HD;
    #pragma unroll
    for (int it = 0; it < 8; it++) {
        int chunk = tid + it * 256;
        int r = chunk >> 4, c8 = (chunk & 15) * 8;
        *(uint4*)&Qs[r * HQS + c8] = *(const uint4*)(Qg + (size_t)r * QKVN + c8);
    }

    float of[16][4];
    #pragma unroll
    for (int nt = 0; nt < 16; nt++)
        #pragma unroll
        for (int r = 0; r < 4; r++) of[nt][r] = 0.f;
    float m_i[2] = {-1e30f, -1e30f}, l_i[2] = {0.f, 0.f};
    const float scale = 0.088388347648318447f;   // 1/sqrt(128)

    int ktiles = 2 * qb + 2;
    for (int kt = 0; kt < ktiles; kt++) {
        int k0 = kt * 64;
        const __half* Kg = QKV + (size_t)(b * SS + k0) * QKVN + HIDD + kvh * HD;
        const __half* Vg = Kg + KVD;

        __syncthreads();
        #pragma unroll
        for (int it = 0; it < 4; it++) {
            int chunk = tid + it * 256;
            int r = chunk >> 4, c8 = (chunk & 15) * 8;
            *(uint4*)&Ks[r * HQS + c8] = *(const uint4*)(Kg + (size_t)r * QKVN + c8);
            *(uint4*)&Vs[r * HQS + c8] = *(const uint4*)(Vg + (size_t)r * QKVN + c8);
        }
        __syncthreads();

        // ---- S = Q K^T : warp tile 16 x 64, 8 k16 steps, ldmatrix frags ----
        float sf[8][4];
        #pragma unroll
        for (int nt = 0; nt < 8; nt++)
            #pragma unroll
            for (int r = 0; r < 4; r++) sf[nt][r] = 0.f;

        #pragma unroll
        for (int kb = 0; kb < 8; kb++) {
            uint32_t af[4], bf[8][2];
            ldsm_x4(af, qs_lm + kb * 32);
            #pragma unroll
            for (int ntp = 0; ntp < 4; ntp++) {
                uint32_t r[4];
                ldsm_x4(r, ks_lm + ntp * (16 * HQS * 2) + kb * 32);
                bf[2 * ntp][0] = r[0]; bf[2 * ntp + 1][0] = r[1];
                bf[2 * ntp][1] = r[2]; bf[2 * ntp + 1][1] = r[3];
            }
            #pragma unroll
            for (int nt = 0; nt < 8; nt++)
                mma_f16(sf[nt], af, bf[nt]);
        }

        // ---- online softmax (rows warp-owned; tig-group shfls) ----
        bool need_mask = (kt >= 2 * qb);
        #pragma unroll
        for (int i = 0; i < 2; i++) {
            int grow = q0 + rbase + i * 8;
            float vmax = -1e30f;
            #pragma unroll
            for (int nt = 0; nt < 8; nt++) {
                float v0 = sf[nt][i * 2 + 0] * scale;
                float v1 = sf[nt][i * 2 + 1] * scale;
                if (need_mask) {
                    int c0 = k0 + nt * 8 + 2 * tig;
                    if (c0 > grow)     v0 = -1e30f;
                    if (c0 + 1 > grow) v1 = -1e30f;
                }
                sf[nt][i * 2 + 0] = v0;
                sf[nt][i * 2 + 1] = v1;
                vmax = fmaxf(vmax, fmaxf(v0, v1));
            }
            vmax = fmaxf(vmax, __shfl_xor_sync(0xffffffffu, vmax, 1));
            vmax = fmaxf(vmax, __shfl_xor_sync(0xffffffffu, vmax, 2));
            float mn = fmaxf(m_i[i], vmax);
            float al = __expf(m_i[i] - mn);
            m_i[i] = mn;
            float rs = 0.f;
            #pragma unroll
            for (int nt = 0; nt < 8; nt++) {
                float e0 = __expf(sf[nt][i * 2 + 0] - mn);
                float e1 = __expf(sf[nt][i * 2 + 1] - mn);
                rs += e0 + e1;
                *(__half2*)((char*)Ps + (rbase + i * 8) * (HPS * 2) + (nt * 8 + 2 * tig) * 2)
                    = __float22half2_rn(make_float2(e0, e1));
            }
            rs += __shfl_xor_sync(0xffffffffu, rs, 1);
            rs += __shfl_xor_sync(0xffffffffu, rs, 2);
            l_i[i] = l_i[i] * al + rs;
            #pragma unroll
            for (int nt = 0; nt < 16; nt++) {
                of[nt][i * 2 + 0] *= al;
                of[nt][i * 2 + 1] *= al;
            }
        }
        __syncwarp();

        // ---- O += P V : 2 passes of 2 k16 steps; V via ldmatrix.trans ----
        #pragma unroll
        for (int pass = 0; pass < 2; pass++) {
            uint32_t pa[2][4];
            const char* pr = (const char*)Ps + rbase * (HPS * 2) + pass * 64 + tig * 4;
            #pragma unroll
            for (int ks = 0; ks < 2; ks++) {
                pa[ks][0] = *(const uint32_t*)(pr + ks * 32);
                pa[ks][1] = *(const uint32_t*)(pr + ks * 32 + 8 * HPS * 2);
                pa[ks][2] = *(const uint32_t*)(pr + ks * 32 + 16);
                pa[ks][3] = *(const uint32_t*)(pr + ks * 32 + 8 * HPS * 2 + 16);
            }
            uint32_t vrow = vs_base + (pass * 32 + lane) * (HQS * 2);
            #pragma unroll
            for (int nt = 0; nt < 16; nt++) {
                uint32_t vb[4];
                ldsm_x4_trans(vb, vrow + nt * 16);
                mma_f16(of[nt], pa[0], vb);
                mma_f16(of[nt], pa[1], vb + 2);
            }
        }
    }

    __half* Yg = Y + (size_t)(b * SS + q0) * HIDD + h * HD;
    #pragma unroll
    for (int i = 0; i < 2; i++) {
        float inv = 1.0f / l_i[i];
        int r = rbase + i * 8;
        #pragma unroll
        for (int nt = 0; nt < 16; nt++) {
            *(__half2*)&Yg[(size_t)r * HIDD + nt * 8 + 2 * tig] =
                __float22half2_rn(make_float2(of[nt][i * 2 + 0] * inv,
                                              of[nt][i * 2 + 1] * inv));
        }
    }
}

// ============================================================================
// Launch
// ============================================================================
extern "C" void kernel_launch(void* const* d_in, const int* in_sizes, int n_in,
                              void* d_out, int out_size)
{
    const float* x  = (const float*)d_in[0];
    const float* cs = (const float*)d_in[1];
    const float* sn = (const float*)d_in[2];
    const float* Wq = (const float*)d_in[3];
    const float* Wk = (const float*)d_in[4];
    const float* Wv = (const float*)d_in[5];
    const float* Wo = (const float*)d_in[6];
    float* out = (float*)d_out;

    __half *xh, *wqkv, *woh, *qkv, *yh;
    cudaGetSymbolAddress((void**)&xh,   g_xh);
    cudaGetSymbolAddress((void**)&wqkv, g_wqkv);
    cudaGetSymbolAddress((void**)&woh,  g_woh);
    cudaGetSymbolAddress((void**)&qkv,  g_qkv);
    cudaGetSymbolAddress((void**)&yh,   g_yh);

    const int M = BB * SS;   // 4096

    cudaFuncSetAttribute(gemm_h,  cudaFuncAttributeMaxDynamicSharedMemorySize, GH_SMEM);
    cudaFuncSetAttribute(flash_h, cudaFuncAttributeMaxDynamicSharedMemorySize, FLASH_H_BYTES);

    // single fused f32 -> f16 conversion pass over all five operands
    f2h_cvt_all<<<(CVT_TOT / 8 + 255) / 256, 256>>>(x, Wq, Wk, Wv, Wo, xh, wqkv, woh);

    // fused QKV projection with RoPE epilogue on q,k columns (< 2560)
    gemm_h<<<dim3(QKVN / 128, M / 128), 256, GH_SMEM>>>(
        xh, wqkv, qkv, M, QKVN, HIDD, 1, cs, sn, HIDD + KVD);

    flash_h<<<dim3(SS / 128, NH, BB), 256, FLASH_H_BYTES>>>(qkv, yh);

    gemm_h<<<dim3(HIDD / 128, M / 128), 256, GH_SMEM>>>(
        yh, woh, out, M, HIDD, HIDD, 0, (const float*)0, (const float*)0, 0);
}